// round 3
// baseline (speedup 1.0000x reference)
#include <cuda_runtime.h>
#include <cuda_fp16.h>

#define N_NODES  20000
#define N_EDGES  40000
#define N_GRAPHS 500
#define D_IN     32
#define D_E      16
#define H1       100
#define H2       20
#define F1       50

#define NB1 1800   // 16*H1 edge-W | H1 bias | H1 root
#define NB2 360    // 16*H2 | H2 | H2

// ---------------- scratch ---------------------------------------------------
__device__ __align__(128) float  d_B1t[D_IN * NB1];
__device__ __align__(128) float  d_B2t[H1 * NB2];
__device__ __align__(128) __half d_Y1h[(size_t)N_NODES * NB1];  // fp16 Y1
__device__ __align__(128) float  d_Y2 [(size_t)N_NODES * NB2];
__device__ __align__(128) float  d_agg1[N_NODES * H1];
__device__ __align__(128) float  d_h1  [N_NODES * H1];
__device__ __align__(128) float  d_agg2[N_NODES * H2];
__device__ __align__(128) float  d_g   [N_GRAPHS * H2];
__device__ __align__(128) float  d_g1  [N_GRAPHS * F1];
__device__ int   d_is64;

// ---------------- packed f32x2 helpers --------------------------------------
__device__ __forceinline__ unsigned long long ffma2(
    unsigned long long a, unsigned long long b, unsigned long long c) {
    unsigned long long d;
    asm("fma.rn.f32x2 %0, %1, %2, %3;" : "=l"(d) : "l"(a), "l"(b), "l"(c));
    return d;
}
__device__ __forceinline__ float2 unpk(unsigned long long v) {
    float2 f;
    asm("mov.b64 {%0,%1}, %2;" : "=f"(f.x), "=f"(f.y) : "l"(v));
    return f;
}
__device__ __forceinline__ void red_v4(float* p, float a, float b, float c, float d) {
    asm volatile("red.global.add.v4.f32 [%0], {%1,%2,%3,%4};"
                 :: "l"(p), "f"(a), "f"(b), "f"(c), "f"(d) : "memory");
}

// ---------------- int32/int64 index detection -------------------------------
__global__ void detect_kernel(const unsigned int* __restrict__ ei_words) {
    __shared__ unsigned int red[256];
    unsigned int v = 0;
    for (int i = threadIdx.x; i < N_EDGES; i += blockDim.x)
        v |= ei_words[2 * i + 1];
    red[threadIdx.x] = v;
    __syncthreads();
    for (int s = 128; s > 0; s >>= 1) {
        if (threadIdx.x < s) red[threadIdx.x] |= red[threadIdx.x + s];
        __syncthreads();
    }
    if (threadIdx.x == 0) d_is64 = (red[0] == 0u) ? 1 : 0;
}

__device__ __forceinline__ int load_idx(const void* p, int i) {
    return d_is64 ? (int)((const long long*)p)[i] : ((const int*)p)[i];
}

// ---------------- build fused B matrices ------------------------------------
__global__ void prep1(const float* __restrict__ W, const float* __restrict__ b,
                      const float* __restrict__ root) {
    int idx = blockIdx.x * blockDim.x + threadIdx.x;
    if (idx >= D_IN * NB1) return;
    int i = idx / NB1, j = idx % NB1;
    float v;
    if (j < 16 * H1)      { int k = j / H1, o = j % H1; v = W[k * (D_IN * H1) + i * H1 + o]; }
    else if (j < 17 * H1) { int o = j - 16 * H1;        v = b[i * H1 + o]; }
    else                  { int o = j - 17 * H1;        v = root[i * H1 + o]; }
    d_B1t[idx] = v;
}
__global__ void prep2(const float* __restrict__ W, const float* __restrict__ b,
                      const float* __restrict__ root) {
    int idx = blockIdx.x * blockDim.x + threadIdx.x;
    if (idx >= H1 * NB2) return;
    int i = idx / NB2, j = idx % NB2;
    float v;
    if (j < 16 * H2)      { int k = j / H2, o = j % H2; v = W[k * (H1 * H2) + i * H2 + o]; }
    else if (j < 17 * H2) { int o = j - 16 * H2;        v = b[i * H2 + o]; }
    else                  { int o = j - 17 * H2;        v = root[i * H2 + o]; }
    d_B2t[idx] = v;
}

// ---------------- zero accumulators (float4) --------------------------------
#define Z4_A1 (N_NODES * H1 / 4)            // 500000
#define Z4_A2 (Z4_A1 + N_NODES * H2 / 4)    // 600000
#define Z4_G  (Z4_A2 + N_GRAPHS * H2 / 4)   // 602500
__global__ void zero_kernel() {
    int i = blockIdx.x * blockDim.x + threadIdx.x;
    float4 z = make_float4(0.f, 0.f, 0.f, 0.f);
    if (i < Z4_A1) ((float4*)d_agg1)[i] = z;
    else if (i < Z4_A2) ((float4*)d_agg2)[i - Z4_A1] = z;
    else if (i < Z4_G)  ((float4*)d_g)[i - Z4_A2] = z;
}

// ---------------- f32x2 GEMM, M-paired accumulators, B duplicated in smem ---
// C[M,N] = A[M,K] @ B[K,N].  128 threads, 8x8 per thread.
// Requires: K % BK == 0, K % 4 == 0, N % 8 == 0.
template<int BM, int BN, int BK, bool HALF_OUT>
__global__ void __launch_bounds__(128) gemm_pk(
    const float* __restrict__ A, int M, int K,
    const float* __restrict__ B, int N,
    void* __restrict__ Cv)
{
    __shared__ float  As[BK][BM];
    __shared__ float2 Bs[BK][BN];

    const int tid  = threadIdx.x;
    const int tx   = tid & 7;     // col group: 8 cols
    const int ty   = tid >> 3;    // row group: 8 rows (16 groups)
    const int row0 = blockIdx.y * BM;
    const int col0 = blockIdx.x * BN;

    unsigned long long acc[4][8];
    #pragma unroll
    for (int p = 0; p < 4; p++)
        #pragma unroll
        for (int j = 0; j < 8; j++) acc[p][j] = 0ull;

    for (int k0 = 0; k0 < K; k0 += BK) {
        // stage A: float4 global loads, scalar smem scatter
        #pragma unroll 2
        for (int s4 = tid; s4 < BM * BK / 4; s4 += 128) {
            int r   = s4 / (BK / 4);
            int kk4 = (s4 % (BK / 4)) * 4;
            int gr  = row0 + r;
            float4 v = (gr < M) ? *(const float4*)&A[(size_t)gr * K + k0 + kk4]
                                : make_float4(0.f, 0.f, 0.f, 0.f);
            As[kk4 + 0][r] = v.x; As[kk4 + 1][r] = v.y;
            As[kk4 + 2][r] = v.z; As[kk4 + 3][r] = v.w;
        }
        // stage B duplicated: Bs[kk][c] = {b, b}
        #pragma unroll 2
        for (int s4 = tid; s4 < BK * BN / 4; s4 += 128) {
            int kk = s4 / (BN / 4);
            int c4 = (s4 % (BN / 4)) * 4;
            int gc = col0 + c4;
            float4 v = (gc < N) ? *(const float4*)&B[(size_t)(k0 + kk) * N + gc]
                                : make_float4(0.f, 0.f, 0.f, 0.f);
            Bs[kk][c4 + 0] = make_float2(v.x, v.x);
            Bs[kk][c4 + 1] = make_float2(v.y, v.y);
            Bs[kk][c4 + 2] = make_float2(v.z, v.z);
            Bs[kk][c4 + 3] = make_float2(v.w, v.w);
        }
        __syncthreads();
        #pragma unroll
        for (int kk = 0; kk < BK; kk++) {
            ulonglong2 a01 = *(const ulonglong2*)&As[kk][ty * 8];
            ulonglong2 a23 = *(const ulonglong2*)&As[kk][ty * 8 + 4];
            unsigned long long av[4] = {a01.x, a01.y, a23.x, a23.y};
            const ulonglong2* bp = (const ulonglong2*)&Bs[kk][tx * 8];
            ulonglong2 b01 = bp[0], b23 = bp[1], b45 = bp[2], b67 = bp[3];
            unsigned long long bv[8] = {b01.x, b01.y, b23.x, b23.y,
                                        b45.x, b45.y, b67.x, b67.y};
            #pragma unroll
            for (int p = 0; p < 4; p++)
                #pragma unroll
                for (int j = 0; j < 8; j++)
                    acc[p][j] = ffma2(av[p], bv[j], acc[p][j]);
        }
        __syncthreads();
    }

    const int cc = col0 + tx * 8;
    if (cc >= N) return;
    #pragma unroll
    for (int p = 0; p < 4; p++) {
        #pragma unroll
        for (int hr = 0; hr < 2; hr++) {
            int r = row0 + ty * 8 + p * 2 + hr;
            if (r >= M) continue;
            float v[8];
            #pragma unroll
            for (int j = 0; j < 8; j++) {
                float2 f = unpk(acc[p][j]);
                v[j] = hr ? f.y : f.x;
            }
            if (HALF_OUT) {
                uint4 u;
                __half2 t0 = __floats2half2_rn(v[0], v[1]);
                __half2 t1 = __floats2half2_rn(v[2], v[3]);
                __half2 t2 = __floats2half2_rn(v[4], v[5]);
                __half2 t3 = __floats2half2_rn(v[6], v[7]);
                u.x = *reinterpret_cast<unsigned int*>(&t0);
                u.y = *reinterpret_cast<unsigned int*>(&t1);
                u.z = *reinterpret_cast<unsigned int*>(&t2);
                u.w = *reinterpret_cast<unsigned int*>(&t3);
                *(uint4*)((__half*)Cv + (size_t)r * N + cc) = u;
            } else {
                float* C = (float*)Cv;
                *(float4*)&C[(size_t)r * N + cc]     = make_float4(v[0], v[1], v[2], v[3]);
                *(float4*)&C[(size_t)r * N + cc + 4] = make_float4(v[4], v[5], v[6], v[7]);
            }
        }
    }
}

// ---------------- edge combine + scatter, layer 1 (fp16 Y1, warp/edge) ------
__global__ void __launch_bounds__(256) combine1(
    const float* __restrict__ ea, const void* __restrict__ ei_raw)
{
    int wid  = threadIdx.x >> 5, lane = threadIdx.x & 31;
    int e    = blockIdx.x * 8 + wid;
    float eaval = (lane < 16) ? ea[e * D_E + lane] : 1.f;
    int src = load_idx(ei_raw, e);
    int dst = load_idx(ei_raw, N_EDGES + e);
    if (lane < 25) {
        const __half* yrow = d_Y1h + (size_t)src * NB1 + lane * 4;
        float a0 = 0.f, a1 = 0.f, a2 = 0.f, a3 = 0.f;
        #pragma unroll
        for (int k = 0; k < 17; k++) {
            float c = __shfl_sync(0x01ffffffu, eaval, k);
            uint2 u = *(const uint2*)(yrow + k * H1);
            __half2 h0 = *reinterpret_cast<__half2*>(&u.x);
            __half2 h1 = *reinterpret_cast<__half2*>(&u.y);
            float2 f0 = __half22float2(h0);
            float2 f1 = __half22float2(h1);
            a0 = fmaf(c, f0.x, a0); a1 = fmaf(c, f0.y, a1);
            a2 = fmaf(c, f1.x, a2); a3 = fmaf(c, f1.y, a3);
        }
        red_v4(d_agg1 + dst * H1 + lane * 4, a0, a1, a2, a3);
    }
}

// ---------------- node update 1 ----------------------------------------------
__global__ void node1ew(const float* __restrict__ bias1) {
    int idx = blockIdx.x * blockDim.x + threadIdx.x;
    if (idx >= N_NODES * H1 / 4) return;
    int n = idx / (H1 / 4), o4 = (idx % (H1 / 4)) * 4;
    float4 a = *(const float4*)&d_agg1[n * H1 + o4];
    uint2 u = *(const uint2*)&d_Y1h[(size_t)n * NB1 + 17 * H1 + o4];
    __half2 h0 = *reinterpret_cast<__half2*>(&u.x);
    __half2 h1 = *reinterpret_cast<__half2*>(&u.y);
    float2 r0 = __half22float2(h0), r1 = __half22float2(h1);
    float4 b = *(const float4*)&bias1[o4];
    float4 out;
    out.x = fmaxf(a.x + r0.x + b.x, 0.f);
    out.y = fmaxf(a.y + r0.y + b.y, 0.f);
    out.z = fmaxf(a.z + r1.x + b.z, 0.f);
    out.w = fmaxf(a.w + r1.y + b.w, 0.f);
    *(float4*)&d_h1[n * H1 + o4] = out;
}

// ---------------- edge combine + scatter, layer 2 -----------------------------
__global__ void __launch_bounds__(256) combine2(
    const float* __restrict__ ea, const void* __restrict__ ei_raw)
{
    __shared__ float ea_s[32][17];
    __shared__ int   sd_s[32][2];
    int tid = threadIdx.x;
    int e0  = blockIdx.x * 32;
    for (int idx = tid; idx < 32 * 17; idx += 256) {
        int el = idx / 17, k = idx % 17;
        ea_s[el][k] = (k < 16) ? ea[(e0 + el) * D_E + k] : 1.f;
    }
    if (tid < 64) {
        int el = tid >> 1, w = tid & 1;
        sd_s[el][w] = load_idx(ei_raw, w * N_EDGES + e0 + el);
    }
    __syncthreads();
    int el = tid >> 3, l = tid & 7;
    if (l < 5) {
        int src = sd_s[el][0], dst = sd_s[el][1];
        const float* yrow = d_Y2 + (size_t)src * NB2 + l * 4;
        float a0 = 0.f, a1 = 0.f, a2 = 0.f, a3 = 0.f;
        #pragma unroll
        for (int k = 0; k < 17; k++) {
            float c = ea_s[el][k];
            float4 y = *(const float4*)(yrow + k * H2);
            a0 = fmaf(c, y.x, a0); a1 = fmaf(c, y.y, a1);
            a2 = fmaf(c, y.z, a2); a3 = fmaf(c, y.w, a3);
        }
        red_v4(d_agg2 + dst * H2 + l * 4, a0, a1, a2, a3);
    }
}

// ---------------- node update 2 + sum-pool -------------------------------------
__global__ void __launch_bounds__(256) node2pool(
    const float* __restrict__ bias2, const void* __restrict__ batch_raw)
{
    int idx = blockIdx.x * blockDim.x + threadIdx.x;
    if (idx >= N_NODES * H2 / 4) return;
    int n = idx / (H2 / 4), c4 = (idx % (H2 / 4)) * 4;
    float4 a = *(const float4*)&d_agg2[n * H2 + c4];
    float4 y = *(const float4*)&d_Y2[(size_t)n * NB2 + 17 * H2 + c4];
    float4 b = *(const float4*)&bias2[c4];
    float v0 = fmaxf(a.x + y.x + b.x, 0.f);
    float v1 = fmaxf(a.y + y.y + b.y, 0.f);
    float v2 = fmaxf(a.z + y.z + b.z, 0.f);
    float v3 = fmaxf(a.w + y.w + b.w, 0.f);
    int g = load_idx(batch_raw, n);
    red_v4(d_g + g * H2 + c4, v0, v1, v2, v3);
}

// ---------------- FCN head -------------------------------------------------------
__global__ void final1_kernel(const float* __restrict__ lin1_W,
                              const float* __restrict__ lin1_b)
{
    int idx = blockIdx.x * blockDim.x + threadIdx.x;
    if (idx < N_GRAPHS * F1) {
        int gi = idx / F1, oo = idx % F1;
        float acc = lin1_b[oo];
        #pragma unroll
        for (int i = 0; i < H2; ++i)
            acc = fmaf(d_g[gi * H2 + i], lin1_W[i * F1 + oo], acc);
        d_g1[idx] = fmaxf(acc, 0.f);
    }
}

__global__ void final2_kernel(const float* __restrict__ lin2_W,
                              const float* __restrict__ lin2_b,
                              float* __restrict__ out)
{
    int gi = blockIdx.x * blockDim.x + threadIdx.x;
    if (gi < N_GRAPHS) {
        float acc = lin2_b[0];
        #pragma unroll
        for (int j = 0; j < F1; ++j)
            acc = fmaf(d_g1[gi * F1 + j], lin2_W[j], acc);
        out[gi] = acc;
    }
}

// ---------------- launch -----------------------------------------------------------
extern "C" void kernel_launch(void* const* d_in, const int* in_sizes, int n_in,
                              void* d_out, int out_size)
{
    const float* x      = (const float*)d_in[0];
    const float* ea     = (const float*)d_in[1];
    const void*  ei     = d_in[2];
    const void*  batch  = d_in[3];
    const float* nn1_W  = (const float*)d_in[4];
    const float* nn1_b  = (const float*)d_in[5];
    const float* root1  = (const float*)d_in[6];
    const float* bias1  = (const float*)d_in[7];
    const float* nn2_W  = (const float*)d_in[8];
    const float* nn2_b  = (const float*)d_in[9];
    const float* root2  = (const float*)d_in[10];
    const float* bias2  = (const float*)d_in[11];
    const float* lin1_W = (const float*)d_in[12];
    const float* lin1_b = (const float*)d_in[13];
    const float* lin2_W = (const float*)d_in[14];
    const float* lin2_b = (const float*)d_in[15];
    float* out = (float*)d_out;

    float *B1t, *B2t, *Y2, *h1;
    __half* Y1h;
    cudaGetSymbolAddress((void**)&B1t, d_B1t);
    cudaGetSymbolAddress((void**)&B2t, d_B2t);
    cudaGetSymbolAddress((void**)&Y1h, d_Y1h);
    cudaGetSymbolAddress((void**)&Y2,  d_Y2);
    cudaGetSymbolAddress((void**)&h1,  d_h1);

    detect_kernel<<<1, 256>>>((const unsigned int*)ei);
    prep1<<<(D_IN * NB1 + 255) / 256, 256>>>(nn1_W, nn1_b, root1);
    prep2<<<(H1 * NB2 + 255) / 256, 256>>>(nn2_W, nn2_b, root2);
    zero_kernel<<<(Z4_G + 255) / 256, 256>>>();

    // Y1[20000,1800](fp16) = x[20000,32] @ B1t[32,1800]   (BK=32: one K-iter)
    gemm_pk<128, 64, 32, true><<<dim3((NB1 + 63) / 64, (N_NODES + 127) / 128), 128>>>(
        x, N_NODES, D_IN, B1t, NB1, (void*)Y1h);
    combine1<<<N_EDGES / 8, 256>>>(ea, ei);
    node1ew<<<(N_NODES * H1 / 4 + 255) / 256, 256>>>(bias1);

    // Y2[20000,360](fp32) = h1[20000,100] @ B2t[100,360]  (BK=20: 5 K-iters)
    gemm_pk<128, 64, 20, false><<<dim3((NB2 + 63) / 64, (N_NODES + 127) / 128), 128>>>(
        h1, N_NODES, H1, B2t, NB2, (void*)Y2);
    combine2<<<N_EDGES / 32, 256>>>(ea, ei);
    node2pool<<<(N_NODES * H2 / 4 + 255) / 256, 256>>>(bias2, batch);

    final1_kernel<<<(N_GRAPHS * F1 + 255) / 256, 256>>>(lin1_W, lin1_b);
    final2_kernel<<<2, 256>>>(lin2_W, lin2_b, out);
}

// round 4
// speedup vs baseline: 1.9559x; 1.9559x over previous
#include <cuda_runtime.h>
#include <cuda_fp16.h>

#define N_NODES  20000
#define N_EDGES  40000
#define N_GRAPHS 500
#define D_IN     32
#define D_E      16
#define H1       100
#define H2       20
#define F1       50

#define NB1 1800   // 16*H1 edge-W | H1 bias | H1 root
#define NB2 360    // 16*H2 | H2 | H2

// ---------------- scratch ---------------------------------------------------
__device__ __align__(128) float  d_B1t[D_IN * NB1];
__device__ __align__(128) float  d_B2t[H1 * NB2];
__device__ __align__(128) __half d_Y1h[(size_t)N_NODES * NB1];  // fp16 (72MB: L2-resident)
__device__ __align__(128) float  d_Y2 [(size_t)N_NODES * NB2];
__device__ __align__(128) float  d_agg1[N_NODES * H1];
__device__ __align__(128) float  d_h1  [N_NODES * H1];
__device__ __align__(128) float  d_agg2[N_NODES * H2];
__device__ __align__(128) float  d_g   [N_GRAPHS * H2];
__device__ __align__(128) float  d_g1  [N_GRAPHS * F1];
__device__ int   d_is64;

// ---------------- packed f32x2 helpers --------------------------------------
__device__ __forceinline__ unsigned long long pk2(float lo, float hi) {
    unsigned long long r;
    asm("mov.b64 %0, {%1,%2};" : "=l"(r) : "f"(lo), "f"(hi));
    return r;
}
__device__ __forceinline__ unsigned long long ffma2(
    unsigned long long a, unsigned long long b, unsigned long long c) {
    unsigned long long d;
    asm("fma.rn.f32x2 %0, %1, %2, %3;" : "=l"(d) : "l"(a), "l"(b), "l"(c));
    return d;
}
__device__ __forceinline__ float2 unpk(unsigned long long v) {
    float2 f;
    asm("mov.b64 {%0,%1}, %2;" : "=f"(f.x), "=f"(f.y) : "l"(v));
    return f;
}
__device__ __forceinline__ void red_v4(float* p, float a, float b, float c, float d) {
    asm volatile("red.global.add.v4.f32 [%0], {%1,%2,%3,%4};"
                 :: "l"(p), "f"(a), "f"(b), "f"(c), "f"(d) : "memory");
}

// ---------------- int32/int64 index detection -------------------------------
__global__ void detect_kernel(const unsigned int* __restrict__ ei_words) {
    __shared__ unsigned int red[256];
    unsigned int v = 0;
    for (int i = threadIdx.x; i < N_EDGES; i += blockDim.x)
        v |= ei_words[2 * i + 1];
    red[threadIdx.x] = v;
    __syncthreads();
    for (int s = 128; s > 0; s >>= 1) {
        if (threadIdx.x < s) red[threadIdx.x] |= red[threadIdx.x + s];
        __syncthreads();
    }
    if (threadIdx.x == 0) d_is64 = (red[0] == 0u) ? 1 : 0;
}

__device__ __forceinline__ int load_idx(const void* p, int i) {
    return d_is64 ? (int)((const long long*)p)[i] : ((const int*)p)[i];
}

// ---------------- build fused B matrices ------------------------------------
__global__ void prep1(const float* __restrict__ W, const float* __restrict__ b,
                      const float* __restrict__ root) {
    int idx = blockIdx.x * blockDim.x + threadIdx.x;
    if (idx >= D_IN * NB1) return;
    int i = idx / NB1, j = idx % NB1;
    float v;
    if (j < 16 * H1)      { int k = j / H1, o = j % H1; v = W[k * (D_IN * H1) + i * H1 + o]; }
    else if (j < 17 * H1) { int o = j - 16 * H1;        v = b[i * H1 + o]; }
    else                  { int o = j - 17 * H1;        v = root[i * H1 + o]; }
    d_B1t[idx] = v;
}
__global__ void prep2(const float* __restrict__ W, const float* __restrict__ b,
                      const float* __restrict__ root) {
    int idx = blockIdx.x * blockDim.x + threadIdx.x;
    if (idx >= H1 * NB2) return;
    int i = idx / NB2, j = idx % NB2;
    float v;
    if (j < 16 * H2)      { int k = j / H2, o = j % H2; v = W[k * (H1 * H2) + i * H2 + o]; }
    else if (j < 17 * H2) { int o = j - 16 * H2;        v = b[i * H2 + o]; }
    else                  { int o = j - 17 * H2;        v = root[i * H2 + o]; }
    d_B2t[idx] = v;
}

// ---------------- zero accumulators (float4) --------------------------------
#define Z4_A1 (N_NODES * H1 / 4)
#define Z4_A2 (Z4_A1 + N_NODES * H2 / 4)
#define Z4_G  (Z4_A2 + N_GRAPHS * H2 / 4)
__global__ void zero_kernel() {
    int i = blockIdx.x * blockDim.x + threadIdx.x;
    float4 z = make_float4(0.f, 0.f, 0.f, 0.f);
    if (i < Z4_A1) ((float4*)d_agg1)[i] = z;
    else if (i < Z4_A2) ((float4*)d_agg2)[i - Z4_A1] = z;
    else if (i < Z4_G)  ((float4*)d_g)[i - Z4_A2] = z;
}

// ---------------- f32x2 tiled GEMM (R2-proven inner loop) --------------------
// C[M,N] = A[M,K] @ B[K,N]. 128 threads, 8x8 per thread, BK=16.
// Crossbar-balanced: 16 floats loaded / 64 FMA per thread-k.
template<int BM, int BN, int BK, bool HALF_OUT>
__global__ void __launch_bounds__(128) gemm_f32x2(
    const float* __restrict__ A, int M, int K,
    const float* __restrict__ B, int N,
    void* __restrict__ Cv)
{
    __shared__ float As[BK][BM + 4];
    __shared__ float Bs[BK][BN];

    const int tid  = threadIdx.x;
    const int tx   = tid & 7;
    const int ty   = tid >> 3;
    const int row0 = blockIdx.y * BM;
    const int col0 = blockIdx.x * BN;

    unsigned long long acc[8][4];
    #pragma unroll
    for (int i = 0; i < 8; i++)
        #pragma unroll
        for (int j = 0; j < 4; j++) acc[i][j] = 0ull;

    for (int k0 = 0; k0 < K; k0 += BK) {
        #pragma unroll
        for (int s = tid; s < BM * BK; s += 128) {
            int r = s / BK, kk = s % BK;
            int gr = row0 + r, gk = k0 + kk;
            As[kk][r] = (gr < M && gk < K) ? A[(size_t)gr * K + gk] : 0.f;
        }
        #pragma unroll
        for (int s = tid; s < BK * BN; s += 128) {
            int kk = s / BN, c = s % BN;
            int gk = k0 + kk, gc = col0 + c;
            Bs[kk][c] = (gk < K && gc < N) ? B[(size_t)gk * N + gc] : 0.f;
        }
        __syncthreads();
        #pragma unroll
        for (int kk = 0; kk < BK; kk++) {
            float4 alo = *(const float4*)&As[kk][ty * 8];
            float4 ahi = *(const float4*)&As[kk][ty * 8 + 4];
            float4 blo = *(const float4*)&Bs[kk][tx * 8];
            float4 bhi = *(const float4*)&Bs[kk][tx * 8 + 4];
            unsigned long long b2[4] = {
                pk2(blo.x, blo.y), pk2(blo.z, blo.w),
                pk2(bhi.x, bhi.y), pk2(bhi.z, bhi.w)
            };
            float av[8] = {alo.x, alo.y, alo.z, alo.w, ahi.x, ahi.y, ahi.z, ahi.w};
            #pragma unroll
            for (int i = 0; i < 8; i++) {
                unsigned long long a2 = pk2(av[i], av[i]);
                #pragma unroll
                for (int j = 0; j < 4; j++)
                    acc[i][j] = ffma2(a2, b2[j], acc[i][j]);
            }
        }
        __syncthreads();
    }

    const int cc = col0 + tx * 8;
    if (cc >= N) return;
    #pragma unroll
    for (int i = 0; i < 8; i++) {
        int r = row0 + ty * 8 + i;
        if (r >= M) continue;
        float2 p0 = unpk(acc[i][0]);
        float2 p1 = unpk(acc[i][1]);
        float2 p2 = unpk(acc[i][2]);
        float2 p3 = unpk(acc[i][3]);
        if (HALF_OUT) {
            uint4 u;
            __half2 t0 = __floats2half2_rn(p0.x, p0.y);
            __half2 t1 = __floats2half2_rn(p1.x, p1.y);
            __half2 t2 = __floats2half2_rn(p2.x, p2.y);
            __half2 t3 = __floats2half2_rn(p3.x, p3.y);
            u.x = *reinterpret_cast<unsigned int*>(&t0);
            u.y = *reinterpret_cast<unsigned int*>(&t1);
            u.z = *reinterpret_cast<unsigned int*>(&t2);
            u.w = *reinterpret_cast<unsigned int*>(&t3);
            *(uint4*)((__half*)Cv + (size_t)r * N + cc) = u;
        } else {
            float* C = (float*)Cv;
            *(float4*)&C[(size_t)r * N + cc]     = make_float4(p0.x, p0.y, p1.x, p1.y);
            *(float4*)&C[(size_t)r * N + cc + 4] = make_float4(p2.x, p2.y, p3.x, p3.y);
        }
    }
}

// ---------------- edge combine + scatter, layer 1 (fp16 Y1, warp/edge) ------
__global__ void __launch_bounds__(256) combine1(
    const float* __restrict__ ea, const void* __restrict__ ei_raw)
{
    int wid  = threadIdx.x >> 5, lane = threadIdx.x & 31;
    int e    = blockIdx.x * 8 + wid;
    float eaval = (lane < 16) ? ea[e * D_E + lane] : 1.f;
    int src = load_idx(ei_raw, e);
    int dst = load_idx(ei_raw, N_EDGES + e);
    if (lane < 25) {
        const __half* yrow = d_Y1h + (size_t)src * NB1 + lane * 4;
        float a0 = 0.f, a1 = 0.f, a2 = 0.f, a3 = 0.f;
        #pragma unroll
        for (int k = 0; k < 17; k++) {
            float c = __shfl_sync(0x01ffffffu, eaval, k);
            uint2 u = *(const uint2*)(yrow + k * H1);
            __half2 h0 = *reinterpret_cast<__half2*>(&u.x);
            __half2 h1 = *reinterpret_cast<__half2*>(&u.y);
            float2 f0 = __half22float2(h0);
            float2 f1 = __half22float2(h1);
            a0 = fmaf(c, f0.x, a0); a1 = fmaf(c, f0.y, a1);
            a2 = fmaf(c, f1.x, a2); a3 = fmaf(c, f1.y, a3);
        }
        red_v4(d_agg1 + dst * H1 + lane * 4, a0, a1, a2, a3);
    }
}

// ---------------- node update 1 ----------------------------------------------
__global__ void node1ew(const float* __restrict__ bias1) {
    int idx = blockIdx.x * blockDim.x + threadIdx.x;
    if (idx >= N_NODES * H1 / 4) return;
    int n = idx / (H1 / 4), o4 = (idx % (H1 / 4)) * 4;
    float4 a = *(const float4*)&d_agg1[n * H1 + o4];
    uint2 u = *(const uint2*)&d_Y1h[(size_t)n * NB1 + 17 * H1 + o4];
    __half2 h0 = *reinterpret_cast<__half2*>(&u.x);
    __half2 h1 = *reinterpret_cast<__half2*>(&u.y);
    float2 r0 = __half22float2(h0), r1 = __half22float2(h1);
    float4 b = *(const float4*)&bias1[o4];
    float4 out;
    out.x = fmaxf(a.x + r0.x + b.x, 0.f);
    out.y = fmaxf(a.y + r0.y + b.y, 0.f);
    out.z = fmaxf(a.z + r1.x + b.z, 0.f);
    out.w = fmaxf(a.w + r1.y + b.w, 0.f);
    *(float4*)&d_h1[n * H1 + o4] = out;
}

// ---------------- edge combine + scatter, layer 2 (R2-proven) ----------------
__global__ void __launch_bounds__(256) combine2(
    const float* __restrict__ ea, const void* __restrict__ ei_raw)
{
    __shared__ float ea_s[8][17];
    __shared__ int src_s[8], dst_s[8];
    int tid = threadIdx.x;
    int el  = tid >> 5;
    int o   = tid & 31;
    int e   = blockIdx.x * 8 + el;
    if (o < 17) ea_s[el][o] = (o < 16) ? ea[e * D_E + o] : 1.f;
    if (o == 17) {
        src_s[el] = load_idx(ei_raw, e);
        dst_s[el] = load_idx(ei_raw, N_EDGES + e);
    }
    __syncthreads();
    if (o < H2) {
        const float* yrow = d_Y2 + (size_t)src_s[el] * NB2 + o;
        float acc = 0.f;
        #pragma unroll
        for (int k = 0; k < 17; k++)
            acc = fmaf(ea_s[el][k], yrow[k * H2], acc);
        atomicAdd(&d_agg2[dst_s[el] * H2 + o], acc);
    }
}

// ---------------- node update 2 + sum-pool ------------------------------------
__global__ void __launch_bounds__(256) node2pool(
    const float* __restrict__ bias2, const void* __restrict__ batch_raw)
{
    int idx = blockIdx.x * blockDim.x + threadIdx.x;
    if (idx >= N_NODES * H2 / 4) return;
    int n = idx / (H2 / 4), c4 = (idx % (H2 / 4)) * 4;
    float4 a = *(const float4*)&d_agg2[n * H2 + c4];
    float4 y = *(const float4*)&d_Y2[(size_t)n * NB2 + 17 * H2 + c4];
    float4 b = *(const float4*)&bias2[c4];
    float v0 = fmaxf(a.x + y.x + b.x, 0.f);
    float v1 = fmaxf(a.y + y.y + b.y, 0.f);
    float v2 = fmaxf(a.z + y.z + b.z, 0.f);
    float v3 = fmaxf(a.w + y.w + b.w, 0.f);
    int g = load_idx(batch_raw, n);
    red_v4(d_g + g * H2 + c4, v0, v1, v2, v3);
}

// ---------------- FCN head -----------------------------------------------------
__global__ void final1_kernel(const float* __restrict__ lin1_W,
                              const float* __restrict__ lin1_b)
{
    int idx = blockIdx.x * blockDim.x + threadIdx.x;
    if (idx < N_GRAPHS * F1) {
        int gi = idx / F1, oo = idx % F1;
        float acc = lin1_b[oo];
        #pragma unroll
        for (int i = 0; i < H2; ++i)
            acc = fmaf(d_g[gi * H2 + i], lin1_W[i * F1 + oo], acc);
        d_g1[idx] = fmaxf(acc, 0.f);
    }
}

__global__ void final2_kernel(const float* __restrict__ lin2_W,
                              const float* __restrict__ lin2_b,
                              float* __restrict__ out)
{
    int gi = blockIdx.x * blockDim.x + threadIdx.x;
    if (gi < N_GRAPHS) {
        float acc = lin2_b[0];
        #pragma unroll
        for (int j = 0; j < F1; ++j)
            acc = fmaf(d_g1[gi * F1 + j], lin2_W[j], acc);
        out[gi] = acc;
    }
}

// ---------------- launch ---------------------------------------------------------
extern "C" void kernel_launch(void* const* d_in, const int* in_sizes, int n_in,
                              void* d_out, int out_size)
{
    const float* x      = (const float*)d_in[0];
    const float* ea     = (const float*)d_in[1];
    const void*  ei     = d_in[2];
    const void*  batch  = d_in[3];
    const float* nn1_W  = (const float*)d_in[4];
    const float* nn1_b  = (const float*)d_in[5];
    const float* root1  = (const float*)d_in[6];
    const float* bias1  = (const float*)d_in[7];
    const float* nn2_W  = (const float*)d_in[8];
    const float* nn2_b  = (const float*)d_in[9];
    const float* root2  = (const float*)d_in[10];
    const float* bias2  = (const float*)d_in[11];
    const float* lin1_W = (const float*)d_in[12];
    const float* lin1_b = (const float*)d_in[13];
    const float* lin2_W = (const float*)d_in[14];
    const float* lin2_b = (const float*)d_in[15];
    float* out = (float*)d_out;

    float *B1t, *B2t, *Y2, *h1;
    __half* Y1h;
    cudaGetSymbolAddress((void**)&B1t, d_B1t);
    cudaGetSymbolAddress((void**)&B2t, d_B2t);
    cudaGetSymbolAddress((void**)&Y1h, d_Y1h);
    cudaGetSymbolAddress((void**)&Y2,  d_Y2);
    cudaGetSymbolAddress((void**)&h1,  d_h1);

    detect_kernel<<<1, 256>>>((const unsigned int*)ei);
    prep1<<<(D_IN * NB1 + 255) / 256, 256>>>(nn1_W, nn1_b, root1);
    prep2<<<(H1 * NB2 + 255) / 256, 256>>>(nn2_W, nn2_b, root2);
    zero_kernel<<<(Z4_G + 255) / 256, 256>>>();

    // Y1[20000,1800](fp16) = x[20000,32] @ B1t[32,1800]
    gemm_f32x2<128, 64, 16, true><<<dim3((NB1 + 63) / 64, (N_NODES + 127) / 128), 128>>>(
        x, N_NODES, D_IN, B1t, NB1, (void*)Y1h);
    combine1<<<N_EDGES / 8, 256>>>(ea, ei);
    node1ew<<<(N_NODES * H1 / 4 + 255) / 256, 256>>>(bias1);

    // Y2[20000,360](fp32) = h1[20000,100] @ B2t[100,360]
    gemm_f32x2<128, 64, 16, false><<<dim3((NB2 + 63) / 64, (N_NODES + 127) / 128), 128>>>(
        h1, N_NODES, H1, B2t, NB2, (void*)Y2);
    combine2<<<N_EDGES / 8, 256>>>(ea, ei);
    node2pool<<<(N_NODES * H2 / 4 + 255) / 256, 256>>>(bias2, batch);

    final1_kernel<<<(N_GRAPHS * F1 + 255) / 256, 256>>>(lin1_W, lin1_b);
    final2_kernel<<<2, 256>>>(lin2_W, lin2_b, out);
}

// round 5
// speedup vs baseline: 2.1599x; 1.1043x over previous
#include <cuda_runtime.h>
#include <cuda_fp16.h>

#define N_NODES  20000
#define N_EDGES  40000
#define N_GRAPHS 500
#define D_IN     32
#define D_E      16
#define H1       100
#define H2       20
#define F1       50

#define NB1 1800   // 16*H1 edge-W | H1 bias | H1 root
#define NB2 360    // 16*H2 | H2 | H2

// ---------------- scratch ---------------------------------------------------
__device__ __align__(128) float  d_B1t[D_IN * NB1];
__device__ __align__(128) float  d_B2t[H1 * NB2];
__device__ __align__(128) __half d_Y1h[(size_t)N_NODES * NB1];  // 72MB fp16
__device__ __align__(128) __half d_Y2h[(size_t)N_NODES * NB2];  // 14.4MB fp16
__device__ __align__(128) float  d_agg1[N_NODES * H1];
__device__ __align__(128) float  d_h1  [N_NODES * H1];
__device__ __align__(128) float  d_agg2[N_NODES * H2];
__device__ __align__(128) float  d_g   [N_GRAPHS * H2];
__device__ int   d_is64;

// ---------------- packed f32x2 helpers --------------------------------------
__device__ __forceinline__ unsigned long long pk2(float lo, float hi) {
    unsigned long long r;
    asm("mov.b64 %0, {%1,%2};" : "=l"(r) : "f"(lo), "f"(hi));
    return r;
}
__device__ __forceinline__ unsigned long long ffma2(
    unsigned long long a, unsigned long long b, unsigned long long c) {
    unsigned long long d;
    asm("fma.rn.f32x2 %0, %1, %2, %3;" : "=l"(d) : "l"(a), "l"(b), "l"(c));
    return d;
}
__device__ __forceinline__ float2 unpk(unsigned long long v) {
    float2 f;
    asm("mov.b64 {%0,%1}, %2;" : "=f"(f.x), "=f"(f.y) : "l"(v));
    return f;
}
__device__ __forceinline__ void red_v4(float* p, float a, float b, float c, float d) {
    asm volatile("red.global.add.v4.f32 [%0], {%1,%2,%3,%4};"
                 :: "l"(p), "f"(a), "f"(b), "f"(c), "f"(d) : "memory");
}

__device__ __forceinline__ int load_idx(const void* p, int i) {
    return d_is64 ? (int)((const long long*)p)[i] : ((const int*)p)[i];
}

// ---------------- fused setup: detect | prep1 | prep2 | zero -----------------
#define NB_PREP1 225    // ceil(32*1800/256)
#define NB_PREP2 141    // ceil(100*360/256)
#define Z4_A1 (N_NODES * H1 / 4)
#define Z4_A2 (Z4_A1 + N_NODES * H2 / 4)
#define Z4_G  (Z4_A2 + N_GRAPHS * H2 / 4)
#define NB_ZERO ((Z4_G + 255) / 256)
#define NB_SETUP (1 + NB_PREP1 + NB_PREP2 + NB_ZERO)

__global__ void __launch_bounds__(256) setup_kernel(
    const unsigned int* __restrict__ ei_words,
    const float* __restrict__ W1, const float* __restrict__ b1,
    const float* __restrict__ root1,
    const float* __restrict__ W2, const float* __restrict__ b2,
    const float* __restrict__ root2)
{
    int blk = blockIdx.x;
    int tid = threadIdx.x;
    if (blk == 0) {
        __shared__ unsigned int red[256];
        unsigned int v = 0;
        for (int i = tid; i < N_EDGES; i += 256)
            v |= ei_words[2 * i + 1];
        red[tid] = v;
        __syncthreads();
        for (int s = 128; s > 0; s >>= 1) {
            if (tid < s) red[tid] |= red[tid + s];
            __syncthreads();
        }
        if (tid == 0) d_is64 = (red[0] == 0u) ? 1 : 0;
        return;
    }
    blk -= 1;
    if (blk < NB_PREP1) {
        int idx = blk * 256 + tid;
        if (idx < D_IN * NB1) {
            int i = idx / NB1, j = idx % NB1;
            float v;
            if (j < 16 * H1)      { int k = j / H1, o = j % H1; v = W1[k * (D_IN * H1) + i * H1 + o]; }
            else if (j < 17 * H1) { int o = j - 16 * H1;        v = b1[i * H1 + o]; }
            else                  { int o = j - 17 * H1;        v = root1[i * H1 + o]; }
            d_B1t[idx] = v;
        }
        return;
    }
    blk -= NB_PREP1;
    if (blk < NB_PREP2) {
        int idx = blk * 256 + tid;
        if (idx < H1 * NB2) {
            int i = idx / NB2, j = idx % NB2;
            float v;
            if (j < 16 * H2)      { int k = j / H2, o = j % H2; v = W2[k * (H1 * H2) + i * H2 + o]; }
            else if (j < 17 * H2) { int o = j - 16 * H2;        v = b2[i * H2 + o]; }
            else                  { int o = j - 17 * H2;        v = root2[i * H2 + o]; }
            d_B2t[idx] = v;
        }
        return;
    }
    blk -= NB_PREP2;
    {
        int i = blk * 256 + tid;
        float4 z = make_float4(0.f, 0.f, 0.f, 0.f);
        if (i < Z4_A1) ((float4*)d_agg1)[i] = z;
        else if (i < Z4_A2) ((float4*)d_agg2)[i - Z4_A1] = z;
        else if (i < Z4_G)  ((float4*)d_g)[i - Z4_A2] = z;
    }
}

// ---------------- f32x2 tiled GEMM (crossbar-balanced, fp16 out) -------------
template<int BM, int BN, int BK>
__global__ void __launch_bounds__(128) gemm_f32x2(
    const float* __restrict__ A, int M, int K,
    const float* __restrict__ B, int N,
    __half* __restrict__ C)
{
    __shared__ float As[BK][BM + 4];
    __shared__ float Bs[BK][BN];

    const int tid  = threadIdx.x;
    const int tx   = tid & 7;
    const int ty   = tid >> 3;
    const int row0 = blockIdx.y * BM;
    const int col0 = blockIdx.x * BN;

    unsigned long long acc[8][4];
    #pragma unroll
    for (int i = 0; i < 8; i++)
        #pragma unroll
        for (int j = 0; j < 4; j++) acc[i][j] = 0ull;

    for (int k0 = 0; k0 < K; k0 += BK) {
        #pragma unroll
        for (int s = tid; s < BM * BK; s += 128) {
            int r = s / BK, kk = s % BK;
            int gr = row0 + r, gk = k0 + kk;
            As[kk][r] = (gr < M && gk < K) ? A[(size_t)gr * K + gk] : 0.f;
        }
        #pragma unroll
        for (int s = tid; s < BK * BN; s += 128) {
            int kk = s / BN, c = s % BN;
            int gk = k0 + kk, gc = col0 + c;
            Bs[kk][c] = (gk < K && gc < N) ? B[(size_t)gk * N + gc] : 0.f;
        }
        __syncthreads();
        #pragma unroll
        for (int kk = 0; kk < BK; kk++) {
            float4 alo = *(const float4*)&As[kk][ty * 8];
            float4 ahi = *(const float4*)&As[kk][ty * 8 + 4];
            float4 blo = *(const float4*)&Bs[kk][tx * 8];
            float4 bhi = *(const float4*)&Bs[kk][tx * 8 + 4];
            unsigned long long b2[4] = {
                pk2(blo.x, blo.y), pk2(blo.z, blo.w),
                pk2(bhi.x, bhi.y), pk2(bhi.z, bhi.w)
            };
            float av[8] = {alo.x, alo.y, alo.z, alo.w, ahi.x, ahi.y, ahi.z, ahi.w};
            #pragma unroll
            for (int i = 0; i < 8; i++) {
                unsigned long long a2 = pk2(av[i], av[i]);
                #pragma unroll
                for (int j = 0; j < 4; j++)
                    acc[i][j] = ffma2(a2, b2[j], acc[i][j]);
            }
        }
        __syncthreads();
    }

    const int cc = col0 + tx * 8;
    if (cc >= N) return;
    #pragma unroll
    for (int i = 0; i < 8; i++) {
        int r = row0 + ty * 8 + i;
        if (r >= M) continue;
        float2 p0 = unpk(acc[i][0]);
        float2 p1 = unpk(acc[i][1]);
        float2 p2 = unpk(acc[i][2]);
        float2 p3 = unpk(acc[i][3]);
        uint4 u;
        __half2 t0 = __floats2half2_rn(p0.x, p0.y);
        __half2 t1 = __floats2half2_rn(p1.x, p1.y);
        __half2 t2 = __floats2half2_rn(p2.x, p2.y);
        __half2 t3 = __floats2half2_rn(p3.x, p3.y);
        u.x = *reinterpret_cast<unsigned int*>(&t0);
        u.y = *reinterpret_cast<unsigned int*>(&t1);
        u.z = *reinterpret_cast<unsigned int*>(&t2);
        u.w = *reinterpret_cast<unsigned int*>(&t3);
        *(uint4*)(C + (size_t)r * N + cc) = u;
    }
}

// ---------------- edge combine + scatter, layer 1 (warp/edge) ----------------
__global__ void __launch_bounds__(256) combine1(
    const float* __restrict__ ea, const void* __restrict__ ei_raw)
{
    int wid  = threadIdx.x >> 5, lane = threadIdx.x & 31;
    int e    = blockIdx.x * 8 + wid;
    float eaval = (lane < 16) ? ea[e * D_E + lane] : 1.f;
    int src = load_idx(ei_raw, e);
    int dst = load_idx(ei_raw, N_EDGES + e);
    if (lane < 25) {
        const __half* yrow = d_Y1h + (size_t)src * NB1 + lane * 4;
        float a0 = 0.f, a1 = 0.f, a2 = 0.f, a3 = 0.f;
        #pragma unroll
        for (int k = 0; k < 17; k++) {
            float c = __shfl_sync(0x01ffffffu, eaval, k);
            uint2 u = *(const uint2*)(yrow + k * H1);
            __half2 h0 = *reinterpret_cast<__half2*>(&u.x);
            __half2 h1 = *reinterpret_cast<__half2*>(&u.y);
            float2 f0 = __half22float2(h0);
            float2 f1 = __half22float2(h1);
            a0 = fmaf(c, f0.x, a0); a1 = fmaf(c, f0.y, a1);
            a2 = fmaf(c, f1.x, a2); a3 = fmaf(c, f1.y, a3);
        }
        red_v4(d_agg1 + dst * H1 + lane * 4, a0, a1, a2, a3);
    }
}

// ---------------- node update 1 ----------------------------------------------
__global__ void node1ew(const float* __restrict__ bias1) {
    int idx = blockIdx.x * blockDim.x + threadIdx.x;
    if (idx >= N_NODES * H1 / 4) return;
    int n = idx / (H1 / 4), o4 = (idx % (H1 / 4)) * 4;
    float4 a = *(const float4*)&d_agg1[n * H1 + o4];
    uint2 u = *(const uint2*)&d_Y1h[(size_t)n * NB1 + 17 * H1 + o4];
    __half2 h0 = *reinterpret_cast<__half2*>(&u.x);
    __half2 h1 = *reinterpret_cast<__half2*>(&u.y);
    float2 r0 = __half22float2(h0), r1 = __half22float2(h1);
    float4 b = *(const float4*)&bias1[o4];
    float4 out;
    out.x = fmaxf(a.x + r0.x + b.x, 0.f);
    out.y = fmaxf(a.y + r0.y + b.y, 0.f);
    out.z = fmaxf(a.z + r1.x + b.z, 0.f);
    out.w = fmaxf(a.w + r1.y + b.w, 0.f);
    *(float4*)&d_h1[n * H1 + o4] = out;
}

// ---------------- edge combine + scatter, layer 2 (fp16 Y2, red_v4) ----------
__global__ void __launch_bounds__(256) combine2(
    const float* __restrict__ ea, const void* __restrict__ ei_raw)
{
    __shared__ float ea_s[32][17];
    __shared__ int   sd_s[32][2];
    int tid = threadIdx.x;
    int e0  = blockIdx.x * 32;
    for (int idx = tid; idx < 32 * 17; idx += 256) {
        int el = idx / 17, k = idx % 17;
        ea_s[el][k] = (k < 16) ? ea[(e0 + el) * D_E + k] : 1.f;
    }
    if (tid < 64) {
        int el = tid >> 1, w = tid & 1;
        sd_s[el][w] = load_idx(ei_raw, w * N_EDGES + e0 + el);
    }
    __syncthreads();
    int el = tid >> 3, l = tid & 7;
    if (l < 5) {
        int src = sd_s[el][0], dst = sd_s[el][1];
        const __half* yrow = d_Y2h + (size_t)src * NB2 + l * 4;
        float a0 = 0.f, a1 = 0.f, a2 = 0.f, a3 = 0.f;
        #pragma unroll
        for (int k = 0; k < 17; k++) {
            float c = ea_s[el][k];
            uint2 u = *(const uint2*)(yrow + k * H2);
            __half2 h0 = *reinterpret_cast<__half2*>(&u.x);
            __half2 h1 = *reinterpret_cast<__half2*>(&u.y);
            float2 f0 = __half22float2(h0);
            float2 f1 = __half22float2(h1);
            a0 = fmaf(c, f0.x, a0); a1 = fmaf(c, f0.y, a1);
            a2 = fmaf(c, f1.x, a2); a3 = fmaf(c, f1.y, a3);
        }
        red_v4(d_agg2 + dst * H2 + l * 4, a0, a1, a2, a3);
    }
}

// ---------------- node update 2 + sum-pool ------------------------------------
__global__ void __launch_bounds__(256) node2pool(
    const float* __restrict__ bias2, const void* __restrict__ batch_raw)
{
    int idx = blockIdx.x * blockDim.x + threadIdx.x;
    if (idx >= N_NODES * H2 / 4) return;
    int n = idx / (H2 / 4), c4 = (idx % (H2 / 4)) * 4;
    float4 a = *(const float4*)&d_agg2[n * H2 + c4];
    uint2 u = *(const uint2*)&d_Y2h[(size_t)n * NB2 + 17 * H2 + c4];
    __half2 h0 = *reinterpret_cast<__half2*>(&u.x);
    __half2 h1 = *reinterpret_cast<__half2*>(&u.y);
    float2 y0 = __half22float2(h0), y1 = __half22float2(h1);
    float4 b = *(const float4*)&bias2[c4];
    float v0 = fmaxf(a.x + y0.x + b.x, 0.f);
    float v1 = fmaxf(a.y + y0.y + b.y, 0.f);
    float v2 = fmaxf(a.z + y1.x + b.z, 0.f);
    float v3 = fmaxf(a.w + y1.y + b.w, 0.f);
    int g = load_idx(batch_raw, n);
    red_v4(d_g + g * H2 + c4, v0, v1, v2, v3);
}

// ---------------- fused FCN head: one block per graph -------------------------
__global__ void __launch_bounds__(64) final_kernel(
    const float* __restrict__ lin1_W, const float* __restrict__ lin1_b,
    const float* __restrict__ lin2_W, const float* __restrict__ lin2_b,
    float* __restrict__ out)
{
    __shared__ float g1s[F1];
    int gi  = blockIdx.x;
    int tid = threadIdx.x;
    if (tid < F1) {
        float acc = lin1_b[tid];
        #pragma unroll
        for (int i = 0; i < H2; ++i)
            acc = fmaf(d_g[gi * H2 + i], lin1_W[i * F1 + tid], acc);
        g1s[tid] = fmaxf(acc, 0.f);
    }
    __syncthreads();
    if (tid < 32) {
        float v = 0.f;
        #pragma unroll
        for (int j = tid; j < F1; j += 32)
            v = fmaf(g1s[j], lin2_W[j], v);
        #pragma unroll
        for (int s = 16; s > 0; s >>= 1)
            v += __shfl_down_sync(0xffffffffu, v, s);
        if (tid == 0) out[gi] = v + lin2_b[0];
    }
}

// ---------------- launch ---------------------------------------------------------
extern "C" void kernel_launch(void* const* d_in, const int* in_sizes, int n_in,
                              void* d_out, int out_size)
{
    const float* x      = (const float*)d_in[0];
    const float* ea     = (const float*)d_in[1];
    const void*  ei     = d_in[2];
    const void*  batch  = d_in[3];
    const float* nn1_W  = (const float*)d_in[4];
    const float* nn1_b  = (const float*)d_in[5];
    const float* root1  = (const float*)d_in[6];
    const float* bias1  = (const float*)d_in[7];
    const float* nn2_W  = (const float*)d_in[8];
    const float* nn2_b  = (const float*)d_in[9];
    const float* root2  = (const float*)d_in[10];
    const float* bias2  = (const float*)d_in[11];
    const float* lin1_W = (const float*)d_in[12];
    const float* lin1_b = (const float*)d_in[13];
    const float* lin2_W = (const float*)d_in[14];
    const float* lin2_b = (const float*)d_in[15];
    float* out = (float*)d_out;

    float *B1t, *B2t, *h1;
    __half *Y1h, *Y2h;
    cudaGetSymbolAddress((void**)&B1t, d_B1t);
    cudaGetSymbolAddress((void**)&B2t, d_B2t);
    cudaGetSymbolAddress((void**)&Y1h, d_Y1h);
    cudaGetSymbolAddress((void**)&Y2h, d_Y2h);
    cudaGetSymbolAddress((void**)&h1,  d_h1);

    setup_kernel<<<NB_SETUP, 256>>>((const unsigned int*)ei,
                                    nn1_W, nn1_b, root1, nn2_W, nn2_b, root2);

    // Y1[20000,1800](fp16) = x[20000,32] @ B1t[32,1800]
    gemm_f32x2<128, 64, 16><<<dim3((NB1 + 63) / 64, (N_NODES + 127) / 128), 128>>>(
        x, N_NODES, D_IN, B1t, NB1, Y1h);
    combine1<<<N_EDGES / 8, 256>>>(ea, ei);
    node1ew<<<(N_NODES * H1 / 4 + 255) / 256, 256>>>(bias1);

    // Y2[20000,360](fp16) = h1[20000,100] @ B2t[100,360]
    gemm_f32x2<128, 64, 16><<<dim3((NB2 + 63) / 64, (N_NODES + 127) / 128), 128>>>(
        h1, N_NODES, H1, B2t, NB2, Y2h);
    combine2<<<N_EDGES / 32, 256>>>(ea, ei);
    node2pool<<<(N_NODES * H2 / 4 + 255) / 256, 256>>>(bias2, batch);

    final_kernel<<<N_GRAPHS, 64>>>(lin1_W, lin1_b, lin2_W, lin2_b, out);
}

// round 7
// speedup vs baseline: 3.8357x; 1.7759x over previous
#include <cuda_runtime.h>
#include <cuda_fp16.h>
#include <cstdint>

#define N_NODES  20000
#define N_EDGES  40000
#define N_GRAPHS 500
#define D_IN     32
#define D_E      16
#define H1       100
#define H2       20
#define F1       50

#define NB1P 1920   // padded N for layer-1 Y (1800 real)
#define NB2P 384    // padded N for layer-2 Y (360 real)
#define K1P  32     // K halves for gemm1 (exact)
#define K2P  128    // padded K halves for gemm2 (100 real)

// ---------------- scratch ---------------------------------------------------
__device__ __align__(128) __half d_xh [(size_t)N_NODES * K1P];
__device__ __align__(128) __half d_B1h[(size_t)NB1P * K1P];      // [N,K] fp16
__device__ __align__(128) __half d_B2h[(size_t)NB2P * K2P];
__device__ __align__(128) __half d_Y1h[(size_t)N_NODES * NB1P];  // 76.8MB
__device__ __align__(128) __half d_Y2h[(size_t)N_NODES * NB2P];
__device__ __align__(128) float  d_agg1[N_NODES * H1];
__device__ __align__(128) __half d_h1h[(size_t)N_NODES * K2P];   // h1 fp16, K-pad
__device__ __align__(128) float  d_agg2[N_NODES * H2];
__device__ __align__(128) float  d_g   [N_GRAPHS * H2];
__device__ int   d_is64;

// ---------------- small helpers ----------------------------------------------
__device__ __forceinline__ void red_v4(float* p, float a, float b, float c, float d) {
    asm volatile("red.global.add.v4.f32 [%0], {%1,%2,%3,%4};"
                 :: "l"(p), "f"(a), "f"(b), "f"(c), "f"(d) : "memory");
}
__device__ __forceinline__ int load_idx(const void* p, int i) {
    return d_is64 ? (int)((const long long*)p)[i] : ((const int*)p)[i];
}
__device__ __forceinline__ uint32_t smem_u32(const void* p) {
    uint32_t a;
    asm("{ .reg .u64 t; cvta.to.shared.u64 t, %1; cvt.u32.u64 %0, t; }"
        : "=r"(a) : "l"(p));
    return a;
}
__device__ __forceinline__ void ldsm_x4(uint32_t& r0, uint32_t& r1,
                                        uint32_t& r2, uint32_t& r3, uint32_t addr) {
    asm volatile("ldmatrix.sync.aligned.m8n8.x4.shared.b16 {%0,%1,%2,%3}, [%4];"
                 : "=r"(r0), "=r"(r1), "=r"(r2), "=r"(r3) : "r"(addr));
}
__device__ __forceinline__ void mma16816(float* c, const uint32_t* a,
                                         uint32_t b0, uint32_t b1) {
    asm volatile(
        "mma.sync.aligned.m16n8k16.row.col.f32.f16.f16.f32 "
        "{%0,%1,%2,%3}, {%4,%5,%6,%7}, {%8,%9}, {%0,%1,%2,%3};"
        : "+f"(c[0]), "+f"(c[1]), "+f"(c[2]), "+f"(c[3])
        : "r"(a[0]), "r"(a[1]), "r"(a[2]), "r"(a[3]), "r"(b0), "r"(b1));
}

// ---------------- fused setup ---------------------------------------------------
#define NB_XH   ((N_NODES * K1P / 8 + 255) / 256)     // 313
#define NB_B1H  ((NB1P * K1P) / 256)                  // 240
#define NB_B2H  ((NB2P * K2P) / 256)                  // 192
#define Z4_A1 (N_NODES * H1 / 4)
#define Z4_A2 (Z4_A1 + N_NODES * H2 / 4)
#define Z4_G  (Z4_A2 + N_GRAPHS * H2 / 4)
#define NB_ZERO ((Z4_G + 255) / 256)
#define NB_SETUP (1 + NB_XH + NB_B1H + NB_B2H + NB_ZERO)

__global__ void __launch_bounds__(256) setup_kernel(
    const unsigned int* __restrict__ ei_words,
    const float* __restrict__ x,
    const float* __restrict__ W1, const float* __restrict__ b1,
    const float* __restrict__ root1,
    const float* __restrict__ W2, const float* __restrict__ b2,
    const float* __restrict__ root2)
{
    int blk = blockIdx.x;
    int tid = threadIdx.x;
    if (blk == 0) {
        __shared__ unsigned int red[256];
        unsigned int v = 0;
        for (int i = tid; i < N_EDGES; i += 256)
            v |= ei_words[2 * i + 1];
        red[tid] = v;
        __syncthreads();
        for (int s = 128; s > 0; s >>= 1) {
            if (tid < s) red[tid] |= red[tid + s];
            __syncthreads();
        }
        if (tid == 0) d_is64 = (red[0] == 0u) ? 1 : 0;
        return;
    }
    blk -= 1;
    if (blk < NB_XH) {  // x -> fp16, 8 halves per thread
        int idx = blk * 256 + tid;
        if (idx < N_NODES * K1P / 8) {
            int n  = idx >> 2;
            int c8 = (idx & 3) * 8;
            const float4 v0 = *(const float4*)&x[n * D_IN + c8];
            const float4 v1 = *(const float4*)&x[n * D_IN + c8 + 4];
            __half2 h0 = __floats2half2_rn(v0.x, v0.y);
            __half2 h1 = __floats2half2_rn(v0.z, v0.w);
            __half2 h2 = __floats2half2_rn(v1.x, v1.y);
            __half2 h3 = __floats2half2_rn(v1.z, v1.w);
            uint4 u;
            u.x = *reinterpret_cast<unsigned int*>(&h0);
            u.y = *reinterpret_cast<unsigned int*>(&h1);
            u.z = *reinterpret_cast<unsigned int*>(&h2);
            u.w = *reinterpret_cast<unsigned int*>(&h3);
            *(uint4*)&d_xh[(size_t)n * K1P + c8] = u;
        }
        return;
    }
    blk -= NB_XH;
    if (blk < NB_B1H) {  // B1h[n][k]
        int idx = blk * 256 + tid;
        int n = idx / K1P, k = idx % K1P;
        float v = 0.f;
        if (n < 1800) {
            if (n < 16 * H1)      { int ke = n / H1, o = n % H1; v = W1[ke * (D_IN * H1) + k * H1 + o]; }
            else if (n < 17 * H1) { int o = n - 16 * H1;         v = b1[k * H1 + o]; }
            else                  { int o = n - 17 * H1;         v = root1[k * H1 + o]; }
        }
        d_B1h[idx] = __float2half(v);
        return;
    }
    blk -= NB_B1H;
    if (blk < NB_B2H) {  // B2h[n][k]
        int idx = blk * 256 + tid;
        int n = idx / K2P, k = idx % K2P;
        float v = 0.f;
        if (n < 360 && k < H1) {
            if (n < 16 * H2)      { int ke = n / H2, o = n % H2; v = W2[ke * (H1 * H2) + k * H2 + o]; }
            else if (n < 17 * H2) { int o = n - 16 * H2;         v = b2[k * H2 + o]; }
            else                  { int o = n - 17 * H2;         v = root2[k * H2 + o]; }
        }
        d_B2h[idx] = __float2half(v);
        return;
    }
    blk -= NB_B2H;
    {
        int i = blk * 256 + tid;
        float4 z = make_float4(0.f, 0.f, 0.f, 0.f);
        if (i < Z4_A1) ((float4*)d_agg1)[i] = z;
        else if (i < Z4_A2) ((float4*)d_agg2)[i - Z4_A1] = z;
        else if (i < Z4_G)  ((float4*)d_g)[i - Z4_A2] = z;
    }
}

// ---------------- mma.sync fp16 GEMM: C[M,Npad] = A[M,KH] @ B[Npad,KH]^T -------
// Block 128x64, 4 warps, warp tile 32x64 (2 m16 x 8 n8). fp32 accumulate.
template<int KH, int BK>
__global__ void __launch_bounds__(128) gemm_mma(
    const __half* __restrict__ A, int M,
    const __half* __restrict__ B,
    __half* __restrict__ C, int Cstride)
{
    constexpr int PITCH = BK + 8;           // halves; +16B pad kills LDSM conflicts
    __shared__ __half As[128 * PITCH];
    __shared__ __half Bs[64 * PITCH];

    const int tid  = threadIdx.x;
    const int wid  = tid >> 5;
    const int lane = tid & 31;
    const int row0 = blockIdx.y * 128;
    const int col0 = blockIdx.x * 64;

    const uint32_t as_base = smem_u32(As);
    const uint32_t bs_base = smem_u32(Bs);

    float acc[2][8][4];
    #pragma unroll
    for (int mt = 0; mt < 2; mt++)
        #pragma unroll
        for (int nt = 0; nt < 8; nt++)
            #pragma unroll
            for (int q = 0; q < 4; q++) acc[mt][nt][q] = 0.f;

    const int l8 = lane & 7;
    const int mi = lane >> 3;

    for (int c0 = 0; c0 < KH; c0 += BK) {
        // ---- stage A: 128 x BK halves, uint4 per thread ----
        #pragma unroll
        for (int it = 0; it < (128 * BK / 8) / 128; it++) {
            int idx = it * 128 + tid;
            int r   = idx / (BK / 8);
            int i8  = (idx % (BK / 8)) * 8;
            int gr  = row0 + r;
            uint4 v = (gr < M) ? *(const uint4*)(A + (size_t)gr * KH + c0 + i8)
                               : make_uint4(0u, 0u, 0u, 0u);
            *(uint4*)(As + r * PITCH + i8) = v;
        }
        // ---- stage B: 64 x BK halves ----
        #pragma unroll
        for (int it = 0; it < (64 * BK / 8) / 128; it++) {
            int idx = it * 128 + tid;
            int r   = idx / (BK / 8);
            int i8  = (idx % (BK / 8)) * 8;
            uint4 v = *(const uint4*)(B + (size_t)(col0 + r) * KH + c0 + i8);
            *(uint4*)(Bs + r * PITCH + i8) = v;
        }
        __syncthreads();

        #pragma unroll
        for (int ks = 0; ks < BK / 16; ks++) {
            uint32_t a[2][4], b[4][4];
            #pragma unroll
            for (int mt = 0; mt < 2; mt++) {
                int row_l = wid * 32 + mt * 16 + l8 + (mi & 1) * 8;
                int kcol  = ks * 16 + (mi >> 1) * 8;
                ldsm_x4(a[mt][0], a[mt][1], a[mt][2], a[mt][3],
                        as_base + (row_l * PITCH + kcol) * 2);
            }
            #pragma unroll
            for (int p = 0; p < 4; p++) {
                int n_l  = p * 16 + l8 + (mi >> 1) * 8;
                int kcol = ks * 16 + (mi & 1) * 8;
                ldsm_x4(b[p][0], b[p][1], b[p][2], b[p][3],
                        bs_base + (n_l * PITCH + kcol) * 2);
            }
            #pragma unroll
            for (int mt = 0; mt < 2; mt++)
                #pragma unroll
                for (int nt = 0; nt < 8; nt++)
                    mma16816(acc[mt][nt], a[mt], b[nt >> 1][(nt & 1) * 2],
                             b[nt >> 1][(nt & 1) * 2 + 1]);
        }
        if (c0 + BK < KH) __syncthreads();
    }

    // ---- store fp16 ----
    #pragma unroll
    for (int mt = 0; mt < 2; mt++) {
        int r_lo = row0 + wid * 32 + mt * 16 + (lane >> 2);
        int r_hi = r_lo + 8;
        #pragma unroll
        for (int nt = 0; nt < 8; nt++) {
            int col = col0 + nt * 8 + 2 * (lane & 3);
            __half2 lo = __floats2half2_rn(acc[mt][nt][0], acc[mt][nt][1]);
            __half2 hi = __floats2half2_rn(acc[mt][nt][2], acc[mt][nt][3]);
            if (r_lo < M) *(__half2*)(C + (size_t)r_lo * Cstride + col) = lo;
            if (r_hi < M) *(__half2*)(C + (size_t)r_hi * Cstride + col) = hi;
        }
    }
}

// ---------------- edge combine + scatter, layer 1 (warp/edge) -----------------
__global__ void __launch_bounds__(256) combine1(
    const float* __restrict__ ea, const void* __restrict__ ei_raw)
{
    int wid  = threadIdx.x >> 5, lane = threadIdx.x & 31;
    int e    = blockIdx.x * 8 + wid;
    float eaval = (lane < 16) ? ea[e * D_E + lane] : 1.f;
    int src = load_idx(ei_raw, e);
    int dst = load_idx(ei_raw, N_EDGES + e);
    if (lane < 25) {
        const __half* yrow = d_Y1h + (size_t)src * NB1P + lane * 4;
        float a0 = 0.f, a1 = 0.f, a2 = 0.f, a3 = 0.f;
        #pragma unroll
        for (int k = 0; k < 17; k++) {
            float c = __shfl_sync(0x01ffffffu, eaval, k);
            uint2 u = *(const uint2*)(yrow + k * H1);
            __half2 h0 = *reinterpret_cast<__half2*>(&u.x);
            __half2 h1 = *reinterpret_cast<__half2*>(&u.y);
            float2 f0 = __half22float2(h0);
            float2 f1 = __half22float2(h1);
            a0 = fmaf(c, f0.x, a0); a1 = fmaf(c, f0.y, a1);
            a2 = fmaf(c, f1.x, a2); a3 = fmaf(c, f1.y, a3);
        }
        red_v4(d_agg1 + dst * H1 + lane * 4, a0, a1, a2, a3);
    }
}

// ---------------- node update 1: h1h fp16 [20000,128] pad ----------------------
__global__ void __launch_bounds__(256) node1ew(const float* __restrict__ bias1) {
    int idx = blockIdx.x * blockDim.x + threadIdx.x;
    if (idx >= N_NODES * 32) return;
    int n = idx >> 5, c4 = (idx & 31) * 4;
    uint2 out;
    if (c4 < H1) {
        float4 a = *(const float4*)&d_agg1[n * H1 + c4];
        uint2 u = *(const uint2*)&d_Y1h[(size_t)n * NB1P + 17 * H1 + c4];
        __half2 h0 = *reinterpret_cast<__half2*>(&u.x);
        __half2 h1 = *reinterpret_cast<__half2*>(&u.y);
        float2 r0 = __half22float2(h0), r1 = __half22float2(h1);
        float4 b = *(const float4*)&bias1[c4];
        __half2 o0 = __floats2half2_rn(fmaxf(a.x + r0.x + b.x, 0.f),
                                       fmaxf(a.y + r0.y + b.y, 0.f));
        __half2 o1 = __floats2half2_rn(fmaxf(a.z + r1.x + b.z, 0.f),
                                       fmaxf(a.w + r1.y + b.w, 0.f));
        out.x = *reinterpret_cast<unsigned int*>(&o0);
        out.y = *reinterpret_cast<unsigned int*>(&o1);
    } else {
        out.x = 0u; out.y = 0u;
    }
    *(uint2*)&d_h1h[(size_t)n * K2P + c4] = out;
}

// ---------------- edge combine + scatter, layer 2 -------------------------------
__global__ void __launch_bounds__(256) combine2(
    const float* __restrict__ ea, const void* __restrict__ ei_raw)
{
    __shared__ float ea_s[32][17];
    __shared__ int   sd_s[32][2];
    int tid = threadIdx.x;
    int e0  = blockIdx.x * 32;
    for (int idx = tid; idx < 32 * 17; idx += 256) {
        int el = idx / 17, k = idx % 17;
        ea_s[el][k] = (k < 16) ? ea[(e0 + el) * D_E + k] : 1.f;
    }
    if (tid < 64) {
        int el = tid >> 1, w = tid & 1;
        sd_s[el][w] = load_idx(ei_raw, w * N_EDGES + e0 + el);
    }
    __syncthreads();
    int el = tid >> 3, l = tid & 7;
    if (l < 5) {
        int src = sd_s[el][0], dst = sd_s[el][1];
        const __half* yrow = d_Y2h + (size_t)src * NB2P + l * 4;
        float a0 = 0.f, a1 = 0.f, a2 = 0.f, a3 = 0.f;
        #pragma unroll
        for (int k = 0; k < 17; k++) {
            float c = ea_s[el][k];
            uint2 u = *(const uint2*)(yrow + k * H2);
            __half2 h0 = *reinterpret_cast<__half2*>(&u.x);
            __half2 h1 = *reinterpret_cast<__half2*>(&u.y);
            float2 f0 = __half22float2(h0);
            float2 f1 = __half22float2(h1);
            a0 = fmaf(c, f0.x, a0); a1 = fmaf(c, f0.y, a1);
            a2 = fmaf(c, f1.x, a2); a3 = fmaf(c, f1.y, a3);
        }
        red_v4(d_agg2 + dst * H2 + l * 4, a0, a1, a2, a3);
    }
}

// ---------------- node update 2 + sum-pool ---------------------------------------
__global__ void __launch_bounds__(256) node2pool(
    const float* __restrict__ bias2, const void* __restrict__ batch_raw)
{
    int idx = blockIdx.x * blockDim.x + threadIdx.x;
    if (idx >= N_NODES * H2 / 4) return;
    int n = idx / (H2 / 4), c4 = (idx % (H2 / 4)) * 4;
    float4 a = *(const float4*)&d_agg2[n * H2 + c4];
    uint2 u = *(const uint2*)&d_Y2h[(size_t)n * NB2P + 17 * H2 + c4];
    __half2 h0 = *reinterpret_cast<__half2*>(&u.x);
    __half2 h1 = *reinterpret_cast<__half2*>(&u.y);
    float2 y0 = __half22float2(h0), y1 = __half22float2(h1);
    float4 b = *(const float4*)&bias2[c4];
    float v0 = fmaxf(a.x + y0.x + b.x, 0.f);
    float v1 = fmaxf(a.y + y0.y + b.y, 0.f);
    float v2 = fmaxf(a.z + y1.x + b.z, 0.f);
    float v3 = fmaxf(a.w + y1.y + b.w, 0.f);
    int g = load_idx(batch_raw, n);
    red_v4(d_g + g * H2 + c4, v0, v1, v2, v3);
}

// ---------------- fused FCN head ---------------------------------------------------
__global__ void __launch_bounds__(64) final_kernel(
    const float* __restrict__ lin1_W, const float* __restrict__ lin1_b,
    const float* __restrict__ lin2_W, const float* __restrict__ lin2_b,
    float* __restrict__ out)
{
    __shared__ float g1s[F1];
    int gi  = blockIdx.x;
    int tid = threadIdx.x;
    if (tid < F1) {
        float acc = lin1_b[tid];
        #pragma unroll
        for (int i = 0; i < H2; ++i)
            acc = fmaf(d_g[gi * H2 + i], lin1_W[i * F1 + tid], acc);
        g1s[tid] = fmaxf(acc, 0.f);
    }
    __syncthreads();
    if (tid < 32) {
        float v = 0.f;
        #pragma unroll
        for (int j = tid; j < F1; j += 32)
            v = fmaf(g1s[j], lin2_W[j], v);
        #pragma unroll
        for (int s = 16; s > 0; s >>= 1)
            v += __shfl_down_sync(0xffffffffu, v, s);
        if (tid == 0) out[gi] = v + lin2_b[0];
    }
}

// ---------------- launch -------------------------------------------------------------
extern "C" void kernel_launch(void* const* d_in, const int* in_sizes, int n_in,
                              void* d_out, int out_size)
{
    const float* x      = (const float*)d_in[0];
    const float* ea     = (const float*)d_in[1];
    const void*  ei     = d_in[2];
    const void*  batch  = d_in[3];
    const float* nn1_W  = (const float*)d_in[4];
    const float* nn1_b  = (const float*)d_in[5];
    const float* root1  = (const float*)d_in[6];
    const float* bias1  = (const float*)d_in[7];
    const float* nn2_W  = (const float*)d_in[8];
    const float* nn2_b  = (const float*)d_in[9];
    const float* root2  = (const float*)d_in[10];
    const float* bias2  = (const float*)d_in[11];
    const float* lin1_W = (const float*)d_in[12];
    const float* lin1_b = (const float*)d_in[13];
    const float* lin2_W = (const float*)d_in[14];
    const float* lin2_b = (const float*)d_in[15];
    float* out = (float*)d_out;

    __half *xh, *B1h, *B2h, *Y1h, *Y2h, *h1h;
    cudaGetSymbolAddress((void**)&xh,  d_xh);
    cudaGetSymbolAddress((void**)&B1h, d_B1h);
    cudaGetSymbolAddress((void**)&B2h, d_B2h);
    cudaGetSymbolAddress((void**)&Y1h, d_Y1h);
    cudaGetSymbolAddress((void**)&Y2h, d_Y2h);
    cudaGetSymbolAddress((void**)&h1h, d_h1h);

    setup_kernel<<<NB_SETUP, 256>>>((const unsigned int*)ei, x,
                                    nn1_W, nn1_b, root1, nn2_W, nn2_b, root2);

    // Y1h[20000,1920] = xh[20000,32] @ B1h[1920,32]^T   (mma.sync fp16)
    gemm_mma<K1P, 32><<<dim3(NB1P / 64, (N_NODES + 127) / 128), 128>>>(
        xh, N_NODES, B1h, Y1h, NB1P);
    combine1<<<N_EDGES / 8, 256>>>(ea, ei);
    node1ew<<<(N_NODES * 32 + 255) / 256, 256>>>(bias1);

    // Y2h[20000,384] = h1h[20000,128] @ B2h[384,128]^T  (mma.sync fp16)
    gemm_mma<K2P, 64><<<dim3(NB2P / 64, (N_NODES + 127) / 128), 128>>>(
        h1h, N_NODES, B2h, Y2h, NB2P);
    combine2<<<N_EDGES / 32, 256>>>(ea, ei);
    node2pool<<<(N_NODES * H2 / 4 + 255) / 256, 256>>>(bias2, batch);

    final_kernel<<<N_GRAPHS, 64>>>(lin1_W, lin1_b, lin2_W, lin2_b, out);
}

// round 8
// speedup vs baseline: 4.0303x; 1.0507x over previous
#include <cuda_runtime.h>
#include <cuda_fp16.h>
#include <cstdint>

#define N_NODES  20000
#define N_EDGES  40000
#define N_GRAPHS 500
#define D_IN     32
#define D_E      16
#define H1       100
#define H2       20
#define F1       50
#define H1P      112            // padded h1 feature width

// ---------------- scratch (all small; L2-resident) ---------------------------
__device__ __align__(128) __half d_xh [(size_t)N_NODES * D_IN];
__device__ __align__(128) __half d_h1h[(size_t)N_NODES * H1P];
__device__ __align__(128) __half d_B1e[17 * 112 * 32];   // [coeff][n][k]
__device__ __align__(128) __half d_B2e[17 * 32 * 112];   // [coeff][n(pad32)][k]
__device__ __align__(128) __half d_R1h[128 * 32];        // root1 [Npad][K]
__device__ __align__(128) __half d_R2h[64 * 112];        // root2 [Npad][K]
__device__ __align__(128) __half d_Y1r[(size_t)N_NODES * 128];
__device__ __align__(128) __half d_Y2r[(size_t)N_NODES * 64];
__device__ __align__(128) float  d_agg1[N_NODES * H1];
__device__ __align__(128) float  d_agg2[N_NODES * H2];
__device__ __align__(128) float  d_g   [N_GRAPHS * H2];
__device__ int   d_is64;

// ---------------- helpers -----------------------------------------------------
__device__ __forceinline__ void red_v4(float* p, float a, float b, float c, float d) {
    asm volatile("red.global.add.v4.f32 [%0], {%1,%2,%3,%4};"
                 :: "l"(p), "f"(a), "f"(b), "f"(c), "f"(d) : "memory");
}
__device__ __forceinline__ void red_v2(float* p, float a, float b) {
    asm volatile("red.global.add.v2.f32 [%0], {%1,%2};"
                 :: "l"(p), "f"(a), "f"(b) : "memory");
}
__device__ __forceinline__ int load_idx(const void* p, int i) {
    return d_is64 ? (int)((const long long*)p)[i] : ((const int*)p)[i];
}
__device__ __forceinline__ uint32_t smem_u32(const void* p) {
    uint32_t a;
    asm("{ .reg .u64 t; cvta.to.shared.u64 t, %1; cvt.u32.u64 %0, t; }"
        : "=r"(a) : "l"(p));
    return a;
}
__device__ __forceinline__ void ldsm_x4(uint32_t& r0, uint32_t& r1,
                                        uint32_t& r2, uint32_t& r3, uint32_t addr) {
    asm volatile("ldmatrix.sync.aligned.m8n8.x4.shared.b16 {%0,%1,%2,%3}, [%4];"
                 : "=r"(r0), "=r"(r1), "=r"(r2), "=r"(r3) : "r"(addr));
}
__device__ __forceinline__ void mma16816(float* c, const uint32_t* a,
                                         uint32_t b0, uint32_t b1) {
    asm volatile(
        "mma.sync.aligned.m16n8k16.row.col.f32.f16.f16.f32 "
        "{%0,%1,%2,%3}, {%4,%5,%6,%7}, {%8,%9}, {%0,%1,%2,%3};"
        : "+f"(c[0]), "+f"(c[1]), "+f"(c[2]), "+f"(c[3])
        : "r"(a[0]), "r"(a[1]), "r"(a[2]), "r"(a[3]), "r"(b0), "r"(b1));
}
__device__ __forceinline__ uint32_t hscale(uint32_t a, __half2 s) {
    __half2 av = *reinterpret_cast<__half2*>(&a);
    __half2 r  = __hmul2(av, s);
    return *reinterpret_cast<uint32_t*>(&r);
}

// ---------------- fused setup ---------------------------------------------------
#define NB_XH   313            // ceil(20000*32/8 / 256)
#define NB_B1E  238            // 17*112*32/256
#define NB_B2E  238            // 17*32*112/256
#define NB_R1   16
#define NB_R2   28
#define Z4_A1 (N_NODES * H1 / 4)
#define Z4_A2 (Z4_A1 + N_NODES * H2 / 4)
#define Z4_G  (Z4_A2 + N_GRAPHS * H2 / 4)
#define NB_ZERO ((Z4_G + 255) / 256)
#define NB_SETUP (1 + NB_XH + NB_B1E + NB_B2E + NB_R1 + NB_R2 + NB_ZERO)

__global__ void __launch_bounds__(256) setup_kernel(
    const unsigned int* __restrict__ ei_words,
    const float* __restrict__ x,
    const float* __restrict__ W1, const float* __restrict__ b1,
    const float* __restrict__ root1,
    const float* __restrict__ W2, const float* __restrict__ b2,
    const float* __restrict__ root2)
{
    int blk = blockIdx.x;
    int tid = threadIdx.x;
    if (blk == 0) {
        __shared__ unsigned int red[256];
        unsigned int v = 0;
        for (int i = tid; i < N_EDGES; i += 256)
            v |= ei_words[2 * i + 1];
        red[tid] = v;
        __syncthreads();
        for (int s = 128; s > 0; s >>= 1) {
            if (tid < s) red[tid] |= red[tid + s];
            __syncthreads();
        }
        if (tid == 0) d_is64 = (red[0] == 0u) ? 1 : 0;
        return;
    }
    blk -= 1;
    if (blk < NB_XH) {          // x -> fp16 [20000,32]
        int idx = blk * 256 + tid;
        if (idx < N_NODES * 4) {
            int n = idx >> 2, c8 = (idx & 3) * 8;
            float4 v0 = *(const float4*)&x[n * D_IN + c8];
            float4 v1 = *(const float4*)&x[n * D_IN + c8 + 4];
            __half2 h0 = __floats2half2_rn(v0.x, v0.y);
            __half2 h1 = __floats2half2_rn(v0.z, v0.w);
            __half2 h2 = __floats2half2_rn(v1.x, v1.y);
            __half2 h3 = __floats2half2_rn(v1.z, v1.w);
            uint4 u;
            u.x = *reinterpret_cast<unsigned int*>(&h0);
            u.y = *reinterpret_cast<unsigned int*>(&h1);
            u.z = *reinterpret_cast<unsigned int*>(&h2);
            u.w = *reinterpret_cast<unsigned int*>(&h3);
            *(uint4*)&d_xh[(size_t)n * D_IN + c8] = u;
        }
        return;
    }
    blk -= NB_XH;
    if (blk < NB_B1E) {         // B1e[c][n][k]
        int idx = blk * 256 + tid;
        int c = idx / 3584, rem = idx % 3584;
        int n = rem / 32, k = rem % 32;
        float v = 0.f;
        if (n < H1) {
            if (c < 16)      v = W1[c * (D_IN * H1) + k * H1 + n];
            else             v = b1[k * H1 + n];
        }
        d_B1e[idx] = __float2half(v);
        return;
    }
    blk -= NB_B1E;
    if (blk < NB_B2E) {         // B2e[c][n][k]
        int idx = blk * 256 + tid;
        int c = idx / 3584, rem = idx % 3584;
        int n = rem / 112, k = rem % 112;
        float v = 0.f;
        if (n < H2 && k < H1) {
            if (c < 16)      v = W2[c * (H1 * H2) + k * H2 + n];
            else             v = b2[k * H2 + n];
        }
        d_B2e[idx] = __float2half(v);
        return;
    }
    blk -= NB_B2E;
    if (blk < NB_R1) {          // root1 [128][32]
        int idx = blk * 256 + tid;
        int n = idx / 32, k = idx % 32;
        d_R1h[idx] = __float2half(n < H1 ? root1[k * H1 + n] : 0.f);
        return;
    }
    blk -= NB_R1;
    if (blk < NB_R2) {          // root2 [64][112]
        int idx = blk * 256 + tid;
        int n = idx / 112, k = idx % 112;
        d_R2h[idx] = __float2half((n < H2 && k < H1) ? root2[k * H2 + n] : 0.f);
        return;
    }
    blk -= NB_R2;
    {
        int i = blk * 256 + tid;
        float4 z = make_float4(0.f, 0.f, 0.f, 0.f);
        if (i < Z4_A1) ((float4*)d_agg1)[i] = z;
        else if (i < Z4_A2) ((float4*)d_agg2)[i - Z4_A1] = z;
        else if (i < Z4_G)  ((float4*)d_g)[i - Z4_A2] = z;
    }
}

// ---------------- mma.sync GEMM (proven R7): C = A[M,KH] @ B[Npad,KH]^T --------
template<int KH, int BK>
__global__ void __launch_bounds__(128) gemm_mma(
    const __half* __restrict__ A, int M,
    const __half* __restrict__ B,
    __half* __restrict__ C, int Cstride)
{
    constexpr int PITCH = BK + 8;
    __shared__ __half As[128 * PITCH];
    __shared__ __half Bs[64 * PITCH];

    const int tid  = threadIdx.x;
    const int wid  = tid >> 5;
    const int lane = tid & 31;
    const int row0 = blockIdx.y * 128;
    const int col0 = blockIdx.x * 64;

    const uint32_t as_base = smem_u32(As);
    const uint32_t bs_base = smem_u32(Bs);

    float acc[2][8][4];
    #pragma unroll
    for (int mt = 0; mt < 2; mt++)
        #pragma unroll
        for (int nt = 0; nt < 8; nt++)
            #pragma unroll
            for (int q = 0; q < 4; q++) acc[mt][nt][q] = 0.f;

    const int l8 = lane & 7;
    const int mi = lane >> 3;

    for (int c0 = 0; c0 < KH; c0 += BK) {
        #pragma unroll
        for (int it = 0; it < (128 * BK / 8) / 128; it++) {
            int idx = it * 128 + tid;
            int r   = idx / (BK / 8);
            int i8  = (idx % (BK / 8)) * 8;
            int gr  = row0 + r;
            uint4 v = (gr < M) ? *(const uint4*)(A + (size_t)gr * KH + c0 + i8)
                               : make_uint4(0u, 0u, 0u, 0u);
            *(uint4*)(As + r * PITCH + i8) = v;
        }
        #pragma unroll
        for (int it = 0; it < (64 * BK / 8) / 128; it++) {
            int idx = it * 128 + tid;
            int r   = idx / (BK / 8);
            int i8  = (idx % (BK / 8)) * 8;
            uint4 v = *(const uint4*)(B + (size_t)(col0 + r) * KH + c0 + i8);
            *(uint4*)(Bs + r * PITCH + i8) = v;
        }
        __syncthreads();

        #pragma unroll
        for (int ks = 0; ks < BK / 16; ks++) {
            uint32_t a[2][4], b[4][4];
            #pragma unroll
            for (int mt = 0; mt < 2; mt++) {
                int row_l = wid * 32 + mt * 16 + l8 + (mi & 1) * 8;
                int kcol  = ks * 16 + (mi >> 1) * 8;
                ldsm_x4(a[mt][0], a[mt][1], a[mt][2], a[mt][3],
                        as_base + (row_l * PITCH + kcol) * 2);
            }
            #pragma unroll
            for (int p = 0; p < 4; p++) {
                int n_l  = p * 16 + l8 + (mi >> 1) * 8;
                int kcol = ks * 16 + (mi & 1) * 8;
                ldsm_x4(b[p][0], b[p][1], b[p][2], b[p][3],
                        bs_base + (n_l * PITCH + kcol) * 2);
            }
            #pragma unroll
            for (int mt = 0; mt < 2; mt++)
                #pragma unroll
                for (int nt = 0; nt < 8; nt++)
                    mma16816(acc[mt][nt], a[mt], b[nt >> 1][(nt & 1) * 2],
                             b[nt >> 1][(nt & 1) * 2 + 1]);
        }
        if (c0 + BK < KH) __syncthreads();
    }

    #pragma unroll
    for (int mt = 0; mt < 2; mt++) {
        int r_lo = row0 + wid * 32 + mt * 16 + (lane >> 2);
        int r_hi = r_lo + 8;
        #pragma unroll
        for (int nt = 0; nt < 8; nt++) {
            int col = col0 + nt * 8 + 2 * (lane & 3);
            __half2 lo = __floats2half2_rn(acc[mt][nt][0], acc[mt][nt][1]);
            __half2 hi = __floats2half2_rn(acc[mt][nt][2], acc[mt][nt][3]);
            if (r_lo < M) *(__half2*)(C + (size_t)r_lo * Cstride + col) = lo;
            if (r_hi < M) *(__half2*)(C + (size_t)r_hi * Cstride + col) = hi;
        }
    }
}

// ---------------- fused edge GEMM 1: msg = (ea ox x[src]) @ W1e, scatter -------
// Block: 128 edges, 256 threads (8 warps x m16 tile). N=112 (100 real), 17 coeffs.
__global__ void __launch_bounds__(256) edge_gemm1(
    const float* __restrict__ ea, const void* __restrict__ ei_raw)
{
    __shared__ __half xs[128 * 40];     // x rows, pitch 40
    __shared__ __half Bs[112 * 40];     // per-coeff W tile [n][k]
    __shared__ __half eas[128 * 17];
    __shared__ int srcs[128], dsts[128];

    const int tid  = threadIdx.x;
    const int w    = tid >> 5;
    const int lane = tid & 31;
    const int l8   = lane & 7;
    const int mi   = lane >> 3;
    const int e0   = blockIdx.x * 128;

    if (tid < 128) {
        int e = e0 + tid, ec = e < N_EDGES ? e : N_EDGES - 1;
        srcs[tid] = load_idx(ei_raw, ec);
        dsts[tid] = load_idx(ei_raw, N_EDGES + ec);
    }
    for (int idx = tid; idx < 128 * 17; idx += 256) {
        int r = idx / 17, c = idx - r * 17;
        int e = e0 + r, ec = e < N_EDGES ? e : N_EDGES - 1;
        eas[idx] = __float2half(c < 16 ? ea[ec * D_E + c] : 1.f);
    }
    __syncthreads();
    for (int idx = tid; idx < 128 * 4; idx += 256) {
        int r = idx >> 2, q = idx & 3;
        *(uint4*)(xs + r * 40 + q * 8) =
            *(const uint4*)(d_xh + (size_t)srcs[r] * D_IN + q * 8);
    }
    __syncthreads();

    // hold A fragments (unscaled x) for both k-steps
    uint32_t afr[2][4];
    {
        int row_l = w * 16 + l8 + (mi & 1) * 8;
        #pragma unroll
        for (int ks = 0; ks < 2; ks++)
            ldsm_x4(afr[ks][0], afr[ks][1], afr[ks][2], afr[ks][3],
                    smem_u32(xs) + (row_l * 40 + ks * 16 + (mi >> 1) * 8) * 2);
    }

    float acc[14][4];
    #pragma unroll
    for (int nt = 0; nt < 14; nt++)
        #pragma unroll
        for (int q = 0; q < 4; q++) acc[nt][q] = 0.f;

    const uint32_t bsb = smem_u32(Bs);
    const int rl0 = w * 16 + (lane >> 2);

    for (int c = 0; c < 17; c++) {
        __syncthreads();
        #pragma unroll
        for (int it = 0; it < 2; it++) {
            int idx = it * 256 + tid;
            if (idx < 448) {
                int n = idx >> 2, q = idx & 3;
                *(uint4*)(Bs + n * 40 + q * 8) =
                    *(const uint4*)(d_B1e + (c * 112 + n) * 32 + q * 8);
            }
        }
        __syncthreads();
        __half2 ca = __half2half2(eas[rl0 * 17 + c]);
        __half2 cb = __half2half2(eas[(rl0 + 8) * 17 + c]);
        #pragma unroll
        for (int ks = 0; ks < 2; ks++) {
            uint32_t sa[4];
            sa[0] = hscale(afr[ks][0], ca);
            sa[1] = hscale(afr[ks][1], cb);
            sa[2] = hscale(afr[ks][2], ca);
            sa[3] = hscale(afr[ks][3], cb);
            #pragma unroll
            for (int p = 0; p < 7; p++) {
                uint32_t b0, b1, b2, b3;
                int n_l = p * 16 + l8 + (mi >> 1) * 8;
                ldsm_x4(b0, b1, b2, b3,
                        bsb + (n_l * 40 + ks * 16 + (mi & 1) * 8) * 2);
                mma16816(acc[2 * p],     sa, b0, b1);
                mma16816(acc[2 * p + 1], sa, b2, b3);
            }
        }
    }

    // scatter: rows rl0, rl0+8 -> agg1[dst]
    int eg0 = e0 + rl0, eg1 = eg0 + 8;
    int dst0 = dsts[rl0], dst1 = dsts[rl0 + 8];
    bool v0 = eg0 < N_EDGES, v1 = eg1 < N_EDGES;
    #pragma unroll
    for (int nt = 0; nt < 13; nt++) {
        int col = nt * 8 + (lane & 3) * 2;
        if (col < H1) {
            if (v0) red_v2(d_agg1 + dst0 * H1 + col, acc[nt][0], acc[nt][1]);
            if (v1) red_v2(d_agg1 + dst1 * H1 + col, acc[nt][2], acc[nt][3]);
        }
    }
}

// ---------------- node update 1: h1h = relu(agg1 + Y1r + b1), padded ----------
__global__ void __launch_bounds__(256) node1ew(const float* __restrict__ bias1) {
    int idx = blockIdx.x * blockDim.x + threadIdx.x;
    if (idx >= N_NODES * 28) return;
    int n = idx / 28, c4 = (idx % 28) * 4;
    uint2 out;
    if (c4 < H1) {
        float4 a = *(const float4*)&d_agg1[n * H1 + c4];
        uint2 u = *(const uint2*)&d_Y1r[(size_t)n * 128 + c4];
        __half2 h0 = *reinterpret_cast<__half2*>(&u.x);
        __half2 h1 = *reinterpret_cast<__half2*>(&u.y);
        float2 r0 = __half22float2(h0), r1 = __half22float2(h1);
        float4 b = *(const float4*)&bias1[c4];
        __half2 o0 = __floats2half2_rn(fmaxf(a.x + r0.x + b.x, 0.f),
                                       fmaxf(a.y + r0.y + b.y, 0.f));
        __half2 o1 = __floats2half2_rn(fmaxf(a.z + r1.x + b.z, 0.f),
                                       fmaxf(a.w + r1.y + b.w, 0.f));
        out.x = *reinterpret_cast<unsigned int*>(&o0);
        out.y = *reinterpret_cast<unsigned int*>(&o1);
    } else {
        out.x = 0u; out.y = 0u;
    }
    *(uint2*)&d_h1h[(size_t)n * H1P + c4] = out;
}

// ---------------- fused edge GEMM 2: msg2 = (ea ox h1[src]) @ W2e, scatter -----
// Block: 128 edges, 256 threads. N=24 real 20, K = 17 x 112.
__global__ void __launch_bounds__(256) edge_gemm2(
    const float* __restrict__ ea, const void* __restrict__ ei_raw)
{
    __shared__ __half hs[128 * 120];    // h1 rows, pitch 120
    __shared__ __half Bs[32 * 120];
    __shared__ __half eas[128 * 17];
    __shared__ int srcs[128], dsts[128];

    const int tid  = threadIdx.x;
    const int w    = tid >> 5;
    const int lane = tid & 31;
    const int l8   = lane & 7;
    const int mi   = lane >> 3;
    const int e0   = blockIdx.x * 128;

    if (tid < 128) {
        int e = e0 + tid, ec = e < N_EDGES ? e : N_EDGES - 1;
        srcs[tid] = load_idx(ei_raw, ec);
        dsts[tid] = load_idx(ei_raw, N_EDGES + ec);
    }
    for (int idx = tid; idx < 128 * 17; idx += 256) {
        int r = idx / 17, c = idx - r * 17;
        int e = e0 + r, ec = e < N_EDGES ? e : N_EDGES - 1;
        eas[idx] = __float2half(c < 16 ? ea[ec * D_E + c] : 1.f);
    }
    __syncthreads();
    for (int idx = tid; idx < 128 * 14; idx += 256) {
        int r = idx / 14, q = idx % 14;
        *(uint4*)(hs + r * 120 + q * 8) =
            *(const uint4*)(d_h1h + (size_t)srcs[r] * H1P + q * 8);
    }
    __syncthreads();

    // hold A fragments: 7 k-steps
    uint32_t afr[7][4];
    {
        int row_l = w * 16 + l8 + (mi & 1) * 8;
        #pragma unroll
        for (int ks = 0; ks < 7; ks++)
            ldsm_x4(afr[ks][0], afr[ks][1], afr[ks][2], afr[ks][3],
                    smem_u32(hs) + (row_l * 120 + ks * 16 + (mi >> 1) * 8) * 2);
    }

    float acc[3][4];
    #pragma unroll
    for (int nt = 0; nt < 3; nt++)
        #pragma unroll
        for (int q = 0; q < 4; q++) acc[nt][q] = 0.f;

    const uint32_t bsb = smem_u32(Bs);
    const int rl0 = w * 16 + (lane >> 2);

    for (int c = 0; c < 17; c++) {
        __syncthreads();
        #pragma unroll
        for (int it = 0; it < 2; it++) {
            int idx = it * 256 + tid;
            if (idx < 448) {
                int n = idx / 14, q = idx % 14;
                *(uint4*)(Bs + n * 120 + q * 8) =
                    *(const uint4*)(d_B2e + (c * 32 + n) * 112 + q * 8);
            }
        }
        __syncthreads();
        __half2 ca = __half2half2(eas[rl0 * 17 + c]);
        __half2 cb = __half2half2(eas[(rl0 + 8) * 17 + c]);
        #pragma unroll
        for (int ks = 0; ks < 7; ks++) {
            uint32_t sa[4];
            sa[0] = hscale(afr[ks][0], ca);
            sa[1] = hscale(afr[ks][1], cb);
            sa[2] = hscale(afr[ks][2], ca);
            sa[3] = hscale(afr[ks][3], cb);
            uint32_t b0, b1, b2, b3;
            int kcol = ks * 16 + (mi & 1) * 8;
            ldsm_x4(b0, b1, b2, b3, bsb + ((l8 + (mi >> 1) * 8) * 120 + kcol) * 2);
            mma16816(acc[0], sa, b0, b1);
            mma16816(acc[1], sa, b2, b3);
            ldsm_x4(b0, b1, b2, b3, bsb + ((16 + l8 + (mi >> 1) * 8) * 120 + kcol) * 2);
            mma16816(acc[2], sa, b0, b1);
        }
    }

    int eg0 = e0 + rl0, eg1 = eg0 + 8;
    int dst0 = dsts[rl0], dst1 = dsts[rl0 + 8];
    bool v0 = eg0 < N_EDGES, v1 = eg1 < N_EDGES;
    #pragma unroll
    for (int nt = 0; nt < 3; nt++) {
        int col = nt * 8 + (lane & 3) * 2;
        if (col < H2) {
            if (v0) red_v2(d_agg2 + dst0 * H2 + col, acc[nt][0], acc[nt][1]);
            if (v1) red_v2(d_agg2 + dst1 * H2 + col, acc[nt][2], acc[nt][3]);
        }
    }
}

// ---------------- node update 2 + sum-pool -------------------------------------
__global__ void __launch_bounds__(256) node2pool(
    const float* __restrict__ bias2, const void* __restrict__ batch_raw)
{
    int idx = blockIdx.x * blockDim.x + threadIdx.x;
    if (idx >= N_NODES * 5) return;
    int n = idx / 5, c4 = (idx % 5) * 4;
    float4 a = *(const float4*)&d_agg2[n * H2 + c4];
    uint2 u = *(const uint2*)&d_Y2r[(size_t)n * 64 + c4];
    __half2 h0 = *reinterpret_cast<__half2*>(&u.x);
    __half2 h1 = *reinterpret_cast<__half2*>(&u.y);
    float2 y0 = __half22float2(h0), y1 = __half22float2(h1);
    float4 b = *(const float4*)&bias2[c4];
    float v0 = fmaxf(a.x + y0.x + b.x, 0.f);
    float v1 = fmaxf(a.y + y0.y + b.y, 0.f);
    float v2 = fmaxf(a.z + y1.x + b.z, 0.f);
    float v3 = fmaxf(a.w + y1.y + b.w, 0.f);
    int g = load_idx(batch_raw, n);
    red_v4(d_g + g * H2 + c4, v0, v1, v2, v3);
}

// ---------------- fused FCN head ---------------------------------------------------
__global__ void __launch_bounds__(64) final_kernel(
    const float* __restrict__ lin1_W, const float* __restrict__ lin1_b,
    const float* __restrict__ lin2_W, const float* __restrict__ lin2_b,
    float* __restrict__ out)
{
    __shared__ float g1s[F1];
    int gi  = blockIdx.x;
    int tid = threadIdx.x;
    if (tid < F1) {
        float acc = lin1_b[tid];
        #pragma unroll
        for (int i = 0; i < H2; ++i)
            acc = fmaf(d_g[gi * H2 + i], lin1_W[i * F1 + tid], acc);
        g1s[tid] = fmaxf(acc, 0.f);
    }
    __syncthreads();
    if (tid < 32) {
        float v = 0.f;
        #pragma unroll
        for (int j = tid; j < F1; j += 32)
            v = fmaf(g1s[j], lin2_W[j], v);
        #pragma unroll
        for (int s = 16; s > 0; s >>= 1)
            v += __shfl_down_sync(0xffffffffu, v, s);
        if (tid == 0) out[gi] = v + lin2_b[0];
    }
}

// ---------------- launch -------------------------------------------------------------
extern "C" void kernel_launch(void* const* d_in, const int* in_sizes, int n_in,
                              void* d_out, int out_size)
{
    const float* x      = (const float*)d_in[0];
    const float* ea     = (const float*)d_in[1];
    const void*  ei     = d_in[2];
    const void*  batch  = d_in[3];
    const float* nn1_W  = (const float*)d_in[4];
    const float* nn1_b  = (const float*)d_in[5];
    const float* root1  = (const float*)d_in[6];
    const float* bias1  = (const float*)d_in[7];
    const float* nn2_W  = (const float*)d_in[8];
    const float* nn2_b  = (const float*)d_in[9];
    const float* root2  = (const float*)d_in[10];
    const float* bias2  = (const float*)d_in[11];
    const float* lin1_W = (const float*)d_in[12];
    const float* lin1_b = (const float*)d_in[13];
    const float* lin2_W = (const float*)d_in[14];
    const float* lin2_b = (const float*)d_in[15];
    float* out = (float*)d_out;

    __half *xh, *h1h, *R1h, *R2h, *Y1r, *Y2r;
    cudaGetSymbolAddress((void**)&xh,  d_xh);
    cudaGetSymbolAddress((void**)&h1h, d_h1h);
    cudaGetSymbolAddress((void**)&R1h, d_R1h);
    cudaGetSymbolAddress((void**)&R2h, d_R2h);
    cudaGetSymbolAddress((void**)&Y1r, d_Y1r);
    cudaGetSymbolAddress((void**)&Y2r, d_Y2r);

    setup_kernel<<<NB_SETUP, 256>>>((const unsigned int*)ei, x,
                                    nn1_W, nn1_b, root1, nn2_W, nn2_b, root2);

    // root term 1: Y1r[20000,128] = xh @ R1h^T
    gemm_mma<32, 32><<<dim3(2, 157), 128>>>(xh, N_NODES, R1h, Y1r, 128);
    // edge messages layer 1 -> agg1
    edge_gemm1<<<(N_EDGES + 127) / 128, 256>>>(ea, ei);
    node1ew<<<(N_NODES * 28 + 255) / 256, 256>>>(bias1);

    // root term 2: Y2r[20000,64] = h1h @ R2h^T
    gemm_mma<112, 112><<<dim3(1, 157), 128>>>(h1h, N_NODES, R2h, Y2r, 64);
    // edge messages layer 2 -> agg2
    edge_gemm2<<<(N_EDGES + 127) / 128, 256>>>(ea, ei);
    node2pool<<<(N_NODES * 5 + 255) / 256, 256>>>(bias2, batch);

    final_kernel<<<N_GRAPHS, 64>>>(lin1_W, lin1_b, lin2_W, lin2_b, out);
}